// round 10
// baseline (speedup 1.0000x reference)
#include <cuda_runtime.h>
#include <cuda_fp16.h>
#include <math.h>
#include <stdint.h>

#define D   768
#define HH  12
#define HS  64
#define BB  8
#define TT  1024
#define TCC 256
#define FFD 3072
#define MQ  (BB*TT)    // 8192 rows
#define MKV (BB*TCC)   // 2048 rows
#define DD  (D*D)

// ---------------- scratch (device globals; no allocs allowed) ----------------
__device__ __half g_ln [MQ*D];
__device__ __half g_q  [MQ*D];                 // cross-attn Q
__device__ __half g_qkv[(size_t)MQ*3*D];       // self-attn fused QKV [8192 x 2304]
__device__ __half g_kvc[(size_t)MKV*2*D];      // cross-attn fused KV [2048 x 1536]
__device__ float  g_x1 [MQ*D];
__device__ float  g_x2 [MQ*D];
__device__ __half g_ctx[MKV*D];                // fp16 context
__device__ __half g_ffh[(size_t)MQ*FFD];
__device__ float  g_part[(size_t)2*MQ*D];      // ff2 split-K partials (fp32)
__device__ __half g_wts[3*DD];                 // repacked self QKV weights [2304 x 768] k-major
__device__ __half g_wtc[3*DD];                 // repacked cross QKV weights
__device__ __half g_w1t[(size_t)FFD*D];        // W1^T : [FF, D]
__device__ __half g_w2t[(size_t)D*FFD];        // W2^T : [D, FF]
__device__ float  g_bqkv[3*D];
__device__ float  g_bkvc[2*D];

// ---------------- helpers ----------------
__device__ __forceinline__ uint32_t smem_u32(const void* p) {
    uint32_t a;
    asm("{ .reg .u64 t; cvta.to.shared.u64 t, %1; cvt.u32.u64 %0, t; }" : "=r"(a) : "l"(p));
    return a;
}
__device__ __forceinline__ void cp_async16(uint32_t dst, const void* src) {
    asm volatile("cp.async.cg.shared.global [%0], [%1], 16;" :: "r"(dst), "l"(src));
}
__device__ __forceinline__ void cp_commit() { asm volatile("cp.async.commit_group;"); }
template<int N> __device__ __forceinline__ void cp_wait() {
    asm volatile("cp.async.wait_group %0;" :: "n"(N));
}
__device__ __forceinline__ void mma_f16(float* c, const uint32_t* a, const uint32_t* b) {
    asm volatile("mma.sync.aligned.m16n8k16.row.col.f32.f16.f16.f32 "
        "{%0,%1,%2,%3}, {%4,%5,%6,%7}, {%8,%9}, {%0,%1,%2,%3};"
        : "+f"(c[0]), "+f"(c[1]), "+f"(c[2]), "+f"(c[3])
        : "r"(a[0]), "r"(a[1]), "r"(a[2]), "r"(a[3]), "r"(b[0]), "r"(b[1]));
}
__device__ __forceinline__ void ldm_x4(uint32_t& r0, uint32_t& r1, uint32_t& r2, uint32_t& r3, uint32_t a) {
    asm volatile("ldmatrix.sync.aligned.m8n8.x4.shared.b16 {%0,%1,%2,%3}, [%4];"
        : "=r"(r0), "=r"(r1), "=r"(r2), "=r"(r3) : "r"(a));
}
__device__ __forceinline__ void ldm_x4t(uint32_t& r0, uint32_t& r1, uint32_t& r2, uint32_t& r3, uint32_t a) {
    asm volatile("ldmatrix.sync.aligned.m8n8.x4.trans.shared.b16 {%0,%1,%2,%3}, [%4];"
        : "=r"(r0), "=r"(r1), "=r"(r2), "=r"(r3) : "r"(a));
}
__device__ __forceinline__ uint32_t packh2(float x, float y) {
    __half2 h = __floats2half2_rn(x, y);
    return *(uint32_t*)&h;
}
__device__ __forceinline__ uint32_t ex2h2(uint32_t x) {
    uint32_t r; asm("ex2.approx.f16x2 %0, %1;" : "=r"(r) : "r"(x));
    return r;
}
__device__ __forceinline__ float silu_f(float z) { return z / (1.0f + expf(-z)); }

// ---------------- LayerNorm: warp-per-row, no smem, fp16 out ----------------
__global__ void ln_kernel(const float* __restrict__ x, const float* __restrict__ w,
                          const float* __restrict__ b, __half* __restrict__ out) {
    int lane = threadIdx.x & 31, wrp = threadIdx.x >> 5;
    int row = blockIdx.x * 8 + wrp;
    const float* xr = x + (size_t)row * D;

    float4 v[6];
    float s = 0.0f, sq = 0.0f;
    #pragma unroll
    for (int j = 0; j < 6; j++) {
        v[j] = *(const float4*)(xr + lane * 4 + j * 128);
        s  += (v[j].x + v[j].y) + (v[j].z + v[j].w);
        sq += v[j].x*v[j].x + v[j].y*v[j].y + v[j].z*v[j].z + v[j].w*v[j].w;
    }
    #pragma unroll
    for (int o = 16; o; o >>= 1) {
        s  += __shfl_xor_sync(0xffffffffu, s,  o);
        sq += __shfl_xor_sync(0xffffffffu, sq, o);
    }
    float mu  = s * (1.0f / D);
    float inv = rsqrtf(sq * (1.0f / D) - mu * mu + 1e-5f);

    __half* orow = out + (size_t)row * D;
    #pragma unroll
    for (int j = 0; j < 6; j++) {
        int c = lane * 4 + j * 128;
        float4 wv = *(const float4*)(w + c);
        float4 bv = *(const float4*)(b + c);
        __half2 h0 = __floats2half2_rn((v[j].x - mu) * inv * wv.x + bv.x,
                                       (v[j].y - mu) * inv * wv.y + bv.y);
        __half2 h1 = __floats2half2_rn((v[j].z - mu) * inv * wv.z + bv.z,
                                       (v[j].w - mu) * inv * wv.w + bv.w);
        uint2 pk = make_uint2(*(uint32_t*)&h0, *(uint32_t*)&h1);
        *(uint2*)(orow + c) = pk;
    }
}

// ------------- repack [H,D,HS] QKV weights -> [N rows, K] k-major fp16 (coalesced) -------------
// grid (HS/32, D/32, 3*H), block (32, 8). Transposes each head's D x HS block.
__global__ void repack_kernel(const float* __restrict__ Wq, const float* __restrict__ Wk,
                              const float* __restrict__ Wv, __half* __restrict__ dst) {
    __shared__ float tile[32][33];
    int m = blockIdx.z / HH, h = blockIdx.z % HH;
    const float* W = (m == 0) ? Wq : ((m == 1) ? Wk : Wv);
    const float* Wh = W + (size_t)h * D * HS;
    int e0 = blockIdx.x * 32, d0 = blockIdx.y * 32;
    #pragma unroll
    for (int i = 0; i < 32; i += 8)
        tile[threadIdx.y + i][threadIdx.x] = Wh[(size_t)(d0 + threadIdx.y + i) * HS + e0 + threadIdx.x];
    __syncthreads();
    __half* dm = dst + (size_t)m * DD;
    #pragma unroll
    for (int i = 0; i < 32; i += 8)
        dm[(size_t)(h * HS + e0 + threadIdx.y + i) * D + d0 + threadIdx.x] =
            __float2half_rn(tile[threadIdx.x][threadIdx.y + i]);
}

// ------------- tiled transpose + fp16 convert -------------
__global__ void transpose_kernel(const float* __restrict__ src, __half* __restrict__ dst,
                                 int R, int C) {
    __shared__ float tile[32][33];
    int bx = blockIdx.x * 32, by = blockIdx.y * 32;
    int x = bx + threadIdx.x;
    #pragma unroll
    for (int i = 0; i < 32; i += 8)
        tile[threadIdx.y + i][threadIdx.x] = src[(size_t)(by + threadIdx.y + i) * C + x];
    __syncthreads();
    int x2 = by + threadIdx.x;
    #pragma unroll
    for (int i = 0; i < 32; i += 8)
        dst[(size_t)(bx + threadIdx.y + i) * R + x2] = __float2half_rn(tile[threadIdx.x][threadIdx.y + i]);
}

__global__ void round_kernel(const float* __restrict__ src, __half* __restrict__ dst, int n) {
    int i = blockIdx.x * blockDim.x + threadIdx.x;
    if (i < n) dst[i] = __float2half_rn(src[i]);
}
__global__ void concat3_kernel(const float* __restrict__ a, const float* __restrict__ b,
                               const float* __restrict__ c, float* __restrict__ dst) {
    int i = blockIdx.x * blockDim.x + threadIdx.x;
    if (i < D) dst[i] = a[i];
    else if (i < 2 * D) dst[i] = b[i - D];
    else if (i < 3 * D) dst[i] = c[i - 2 * D];
}
__global__ void concat2_kernel(const float* __restrict__ a, const float* __restrict__ b,
                               float* __restrict__ dst) {
    int i = blockIdx.x * blockDim.x + threadIdx.x;
    if (i < D) dst[i] = a[i];
    else if (i < 2 * D) dst[i] = b[i - D];
}

// ------------- split-K reduction: out = p0 + p1 + bias + res -------------
__global__ void reduce2_kernel(const float* __restrict__ p, const float* __restrict__ bias,
                               const float* __restrict__ res, float* __restrict__ out) {
    int i = blockIdx.x * blockDim.x + threadIdx.x;        // float4 index
    size_t e0 = (size_t)i * 4;
    int col = (int)(e0 % D);
    float4 a = *(const float4*)(p + e0);
    float4 b = *(const float4*)(p + (size_t)MQ * D + e0);
    float4 bs = *(const float4*)(bias + col);
    float4 rr = *(const float4*)(res + e0);
    float4 o;
    o.x = a.x + b.x + bs.x + rr.x;
    o.y = a.y + b.y + bs.y + rr.y;
    o.z = a.z + b.z + bs.z + rr.z;
    o.w = a.w + b.w + bs.w + rr.w;
    *(float4*)(out + e0) = o;
}

// =======================================================================================
// fp16 mma.sync GEMM: BM=BN=128, BK=32, 256 threads, 5-stage cp.async, ldmatrix frags.
// SPLITK>1: blockIdx.z selects K-chunk; writes fp32 partials (no bias/res/act).
// =======================================================================================
#define WS     20
#define STAGES 5
#define TILEWW (128 * WS)

template<int ACT, bool RES, bool OUTH, int SPLITK>
__global__ __launch_bounds__(256)
void gemm_mma(const __half* __restrict__ A, const __half* __restrict__ Bt,
              const float* __restrict__ bias, const float* __restrict__ res,
              void* __restrict__ Cv, int M, int N, int K) {
    extern __shared__ uint32_t smw[];

    const int tid  = threadIdx.x;
    const int lane = tid & 31, wid = tid >> 5;
    const int warp_m = wid & 1, warp_n = wid >> 1;
    const int bm = blockIdx.y * 128, bn = blockIdx.x * 128;
    const uint32_t sbase = smem_u32(smw);

    const int Ks = K / SPLITK;
    const int kz = (SPLITK > 1) ? blockIdx.z : 0;

    const int r0l = tid >> 2, subl = tid & 3;
    const __half* Ag = A + (size_t)(bm + r0l) * K + kz * Ks + subl * 8;
    const __half* Bg = Bt + (size_t)(bn + r0l) * K + kz * Ks + subl * 8;
    const uint32_t adst0 = sbase + (uint32_t)(r0l * WS + subl * 4) * 4u;
    const uint32_t bdst0 = sbase + (uint32_t)(STAGES * TILEWW + r0l * WS + subl * 4) * 4u;

    const int nt = Ks >> 5;

    auto prefetch = [&](int kt) {
        int s = kt % STAGES;
        uint32_t ad = adst0 + (uint32_t)(s * TILEWW) * 4u;
        uint32_t bd = bdst0 + (uint32_t)(s * TILEWW) * 4u;
        const __half* ag = Ag + kt * 32;
        const __half* bg = Bg + kt * 32;
        cp_async16(ad, ag);
        cp_async16(ad + (uint32_t)(64 * WS) * 4u, ag + (size_t)64 * K);
        cp_async16(bd, bg);
        cp_async16(bd + (uint32_t)(64 * WS) * 4u, bg + (size_t)64 * K);
    };

    float acc[4][4][4];
    #pragma unroll
    for (int mi = 0; mi < 4; mi++)
        #pragma unroll
        for (int ni = 0; ni < 4; ni++)
            #pragma unroll
            for (int e = 0; e < 4; e++) acc[mi][ni][e] = 0.0f;

    #pragma unroll
    for (int s = 0; s < STAGES - 1; s++) { prefetch(s); cp_commit(); }

    const uint32_t a_l = (uint32_t)((warp_m * 64 + (lane & 15)) * WS) * 4u + (uint32_t)((lane >> 4) * 16);
    const uint32_t b_l = (uint32_t)(STAGES * TILEWW) * 4u +
                         (uint32_t)((warp_n * 32 + (lane & 7) + ((lane >> 4) << 3)) * WS) * 4u +
                         (uint32_t)(((lane >> 3) & 1) * 16);

    for (int kt = 0; kt < nt; kt++) {
        cp_wait<STAGES - 2>();
        __syncthreads();
        if (kt + STAGES - 1 < nt) prefetch(kt + STAGES - 1);
        cp_commit();

        int s = kt % STAGES;
        const uint32_t soff = (uint32_t)(s * TILEWW) * 4u;
        const uint32_t abase_s = sbase + soff + a_l;
        const uint32_t bbase_s = sbase + soff + b_l;

        #pragma unroll
        for (int ks = 0; ks < 2; ks++) {
            const uint32_t koff = (uint32_t)(ks * 32);
            uint32_t af[4][4], bf[4][2];
            #pragma unroll
            for (int mi = 0; mi < 4; mi++)
                ldm_x4(af[mi][0], af[mi][1], af[mi][2], af[mi][3],
                       abase_s + (uint32_t)(mi * 16 * WS) * 4u + koff);
            ldm_x4(bf[0][0], bf[0][1], bf[1][0], bf[1][1], bbase_s + koff);
            ldm_x4(bf[2][0], bf[2][1], bf[3][0], bf[3][1],
                   bbase_s + (uint32_t)(16 * WS) * 4u + koff);
            #pragma unroll
            for (int mi = 0; mi < 4; mi++)
                #pragma unroll
                for (int ni = 0; ni < 4; ni++)
                    mma_f16(acc[mi][ni], af[mi], bf[ni]);
        }
    }

    const int lr = lane >> 2, lc = lane & 3;
    #pragma unroll
    for (int mi = 0; mi < 4; mi++) {
        int r0 = bm + warp_m * 64 + mi * 16 + lr;
        #pragma unroll
        for (int ni = 0; ni < 4; ni++) {
            int c0 = bn + warp_n * 32 + ni * 8 + 2 * lc;
            if (SPLITK > 1) {
                float* Cf = (float*)Cv + (size_t)kz * M * N;
                *(float2*)(Cf + (size_t)r0 * N + c0)       = make_float2(acc[mi][ni][0], acc[mi][ni][1]);
                *(float2*)(Cf + (size_t)(r0 + 8) * N + c0) = make_float2(acc[mi][ni][2], acc[mi][ni][3]);
                continue;
            }
            float b0 = bias[c0], b1 = bias[c0 + 1];
            float v00 = acc[mi][ni][0] + b0, v01 = acc[mi][ni][1] + b1;
            float v10 = acc[mi][ni][2] + b0, v11 = acc[mi][ni][3] + b1;
            if (ACT == 1) { v00 = silu_f(v00); v01 = silu_f(v01); v10 = silu_f(v10); v11 = silu_f(v11); }
            if (RES) {
                const float2 rA = *(const float2*)(res + (size_t)r0 * N + c0);
                const float2 rB = *(const float2*)(res + (size_t)(r0 + 8) * N + c0);
                v00 += rA.x; v01 += rA.y; v10 += rB.x; v11 += rB.y;
            }
            if (OUTH) {
                __half* Ch = (__half*)Cv;
                uint32_t p0 = packh2(v00, v01), p1 = packh2(v10, v11);
                *(uint32_t*)(Ch + (size_t)r0 * N + c0)       = p0;
                *(uint32_t*)(Ch + (size_t)(r0 + 8) * N + c0) = p1;
            } else {
                float* Cf = (float*)Cv;
                *(float2*)(Cf + (size_t)r0 * N + c0)       = make_float2(v00, v01);
                *(float2*)(Cf + (size_t)(r0 + 8) * N + c0) = make_float2(v10, v11);
            }
        }
    }
}

// =======================================================================================
// fp16 tensor-core flash attention: f16x2 exp2 + ones-MMA row sums.
// =======================================================================================
#define KVSTR_B 144
#define KTILE_B (64 * KVSTR_B)
#define ONESH2  0x3C003C00u

__global__ __launch_bounds__(256)
void attn_tc(const __half* __restrict__ Q, int ldq,
             const __half* __restrict__ Kg, const __half* __restrict__ Vg, int ldkv,
             const float* __restrict__ xres, float* __restrict__ out,
             int Tq, int Tkv) {
    extern __shared__ uint32_t smw[];
    const uint32_t sbase = smem_u32(smw);

    const int tid = threadIdx.x;
    const int lane = tid & 31, wid = tid >> 5;
    const int lr = lane >> 2, lc = lane & 3;
    const int h = blockIdx.y, b = blockIdx.z;
    const int brow = b * Tq + blockIdx.x * 128;
    const int m0 = wid * 16;

    const __half* Kb = Kg + (size_t)b * Tkv * ldkv + h * HS;
    const __half* Vb = Vg + (size_t)b * Tkv * ldkv + h * HS;

    const float SC2 = 0.125f * 1.4426950408889634f;
    uint32_t qf[4][4];
    {
        const __half* Qp = Q + (size_t)(brow + m0) * ldq + h * HS;
        #pragma unroll
        for (int ks = 0; ks < 4; ks++) {
            int c = ks * 16 + 2 * lc;
            #pragma unroll
            for (int e = 0; e < 4; e++) {
                int rr = (e & 1) ? lr + 8 : lr;
                int cc = c + ((e >> 1) ? 8 : 0);
                __half2 hv = *(const __half2*)(Qp + (size_t)rr * ldq + cc);
                float2 f = __half22float2(hv);
                qf[ks][e] = packh2(f.x * SC2, f.y * SC2);
            }
        }
    }

    const int rl = lane & 7;
    const uint32_t loff_k = (uint32_t)(rl * KVSTR_B + ((lane >> 3) * 16));
    const uint32_t loff_v = (uint32_t)(((((lane >> 3) & 1) * 8 + rl) * KVSTR_B) + ((lane >> 4) * 16));

    const int lrow = tid >> 3, lsub = tid & 7;
    auto prefetch = [&](int kt) {
        int buf = kt & 1;
        uint32_t kdst = sbase + buf * KTILE_B + lrow * KVSTR_B + lsub * 16;
        uint32_t vdst = kdst + 2 * KTILE_B;
        const __half* kp = Kb + (size_t)(kt * 64 + lrow) * ldkv + lsub * 8;
        const __half* vp = Vb + (size_t)(kt * 64 + lrow) * ldkv + lsub * 8;
        cp_async16(kdst, kp);
        cp_async16(kdst + 32 * KVSTR_B, kp + (size_t)32 * ldkv);
        cp_async16(vdst, vp);
        cp_async16(vdst + 32 * KVSTR_B, vp + (size_t)32 * ldkv);
    };

    float oacc[8][4];
    #pragma unroll
    for (int i = 0; i < 8; i++)
        #pragma unroll
        for (int e = 0; e < 4; e++) oacc[i][e] = 0.0f;
    float lacc[4] = {0.0f, 0.0f, 0.0f, 0.0f};
    float mstate0 = -1e30f, mstate1 = -1e30f;

    const int nt = Tkv >> 6;
    prefetch(0); cp_commit();

    for (int kt = 0; kt < nt; kt++) {
        if (kt + 1 < nt) { prefetch(kt + 1); cp_commit(); cp_wait<1>(); }
        else             { cp_wait<0>(); }
        __syncthreads();

        const uint32_t kbase = sbase + (kt & 1) * KTILE_B;
        const uint32_t vbase = kbase + 2 * KTILE_B;

        float sacc[8][4];
        #pragma unroll
        for (int nf = 0; nf < 8; nf++)
            #pragma unroll
            for (int e = 0; e < 4; e++) sacc[nf][e] = 0.0f;

        #pragma unroll
        for (int nf = 0; nf < 8; nf++) {
            uint32_t k0, k1, k2, k3, k4, k5, k6, k7;
            uint32_t base = kbase + nf * (8 * KVSTR_B) + loff_k;
            ldm_x4(k0, k1, k2, k3, base);
            ldm_x4(k4, k5, k6, k7, base + 64);
            uint32_t bf[2];
            bf[0] = k0; bf[1] = k1; mma_f16(sacc[nf], qf[0], bf);
            bf[0] = k2; bf[1] = k3; mma_f16(sacc[nf], qf[1], bf);
            bf[0] = k4; bf[1] = k5; mma_f16(sacc[nf], qf[2], bf);
            bf[0] = k6; bf[1] = k7; mma_f16(sacc[nf], qf[3], bf);
        }

        float mx0 = -1e30f, mx1 = -1e30f;
        #pragma unroll
        for (int nf = 0; nf < 8; nf++) {
            mx0 = fmaxf(mx0, fmaxf(sacc[nf][0], sacc[nf][1]));
            mx1 = fmaxf(mx1, fmaxf(sacc[nf][2], sacc[nf][3]));
        }
        mx0 = fmaxf(mx0, __shfl_xor_sync(0xffffffffu, mx0, 1));
        mx0 = fmaxf(mx0, __shfl_xor_sync(0xffffffffu, mx0, 2));
        mx1 = fmaxf(mx1, __shfl_xor_sync(0xffffffffu, mx1, 1));
        mx1 = fmaxf(mx1, __shfl_xor_sync(0xffffffffu, mx1, 2));
        float mn0 = fmaxf(mstate0, mx0), mn1 = fmaxf(mstate1, mx1);
        float corr0 = exp2f(mstate0 - mn0), corr1 = exp2f(mstate1 - mn1);
        mstate0 = mn0; mstate1 = mn1;

        uint32_t pf[8][2];
        #pragma unroll
        for (int nf = 0; nf < 8; nf++) {
            pf[nf][0] = ex2h2(packh2(sacc[nf][0] - mn0, sacc[nf][1] - mn0));
            pf[nf][1] = ex2h2(packh2(sacc[nf][2] - mn1, sacc[nf][3] - mn1));
        }

        #pragma unroll
        for (int nf = 0; nf < 8; nf++) {
            oacc[nf][0] *= corr0; oacc[nf][1] *= corr0;
            oacc[nf][2] *= corr1; oacc[nf][3] *= corr1;
        }
        lacc[0] *= corr0; lacc[1] *= corr0; lacc[2] *= corr1; lacc[3] *= corr1;

        const uint32_t onesf[2] = {ONESH2, ONESH2};
        #pragma unroll
        for (int kg = 0; kg < 4; kg++) {
            uint32_t af[4];
            af[0] = pf[2*kg][0];
            af[1] = pf[2*kg][1];
            af[2] = pf[2*kg+1][0];
            af[3] = pf[2*kg+1][1];
            mma_f16(lacc, af, onesf);
            #pragma unroll
            for (int nfp = 0; nfp < 4; nfp++) {
                uint32_t v0, v1, v2, v3;
                ldm_x4t(v0, v1, v2, v3, vbase + kg * (16 * KVSTR_B) + nfp * 32 + loff_v);
                uint32_t bf[2];
                bf[0] = v0; bf[1] = v1; mma_f16(oacc[2*nfp],     af, bf);
                bf[0] = v2; bf[1] = v3; mma_f16(oacc[2*nfp + 1], af, bf);
            }
        }
        __syncthreads();
    }

    float inv0 = 1.0f / lacc[0], inv1 = 1.0f / lacc[2];
    int row0 = brow + m0 + lr, row1 = row0 + 8;
    #pragma unroll
    for (int nf = 0; nf < 8; nf++) {
        int col = h * HS + nf * 8 + 2 * lc;
        float2 rA = *(const float2*)(xres + (size_t)row0 * D + col);
        float2 rB = *(const float2*)(xres + (size_t)row1 * D + col);
        *(float2*)(out + (size_t)row0 * D + col) =
            make_float2(rA.x + oacc[nf][0] * inv0, rA.y + oacc[nf][1] * inv0);
        *(float2*)(out + (size_t)row1 * D + col) =
            make_float2(rB.x + oacc[nf][2] * inv1, rB.y + oacc[nf][3] * inv1);
    }
}

// ---------------- host launch (multi-stream overlap inside the graph) ----------------
extern "C" void kernel_launch(void* const* d_in, const int* in_sizes, int n_in,
                              void* d_out, int out_size) {
    const float* x0    = (const float*)d_in[0];
    const float* ctx   = (const float*)d_in[1];
    const float* ln1_w = (const float*)d_in[2];
    const float* ln1_b = (const float*)d_in[3];
    const float* sWq   = (const float*)d_in[4];
    const float* sbq   = (const float*)d_in[5];
    const float* sWk   = (const float*)d_in[6];
    const float* sbk   = (const float*)d_in[7];
    const float* sWv   = (const float*)d_in[8];
    const float* sbv   = (const float*)d_in[9];
    const float* ln2_w = (const float*)d_in[10];
    const float* ln2_b = (const float*)d_in[11];
    const float* cWq   = (const float*)d_in[12];
    const float* cbq   = (const float*)d_in[13];
    const float* cWk   = (const float*)d_in[14];
    const float* cbk   = (const float*)d_in[15];
    const float* cWv   = (const float*)d_in[16];
    const float* cbv   = (const float*)d_in[17];
    const float* ln3_w = (const float*)d_in[18];
    const float* ln3_b = (const float*)d_in[19];
    const float* W1    = (const float*)d_in[20];
    const float* b1    = (const float*)d_in[21];
    const float* W2    = (const float*)d_in[22];
    const float* b2    = (const float*)d_in[23];
    float* outp = (float*)d_out;

    __half *ln, *q, *qkv, *kvc, *ctr, *ffh, *wts, *wtc, *w1t, *w2t;
    float *x1, *x2, *bqkv, *bkvc, *part;
    cudaGetSymbolAddress((void**)&ln,   g_ln);
    cudaGetSymbolAddress((void**)&q,    g_q);
    cudaGetSymbolAddress((void**)&qkv,  g_qkv);
    cudaGetSymbolAddress((void**)&kvc,  g_kvc);
    cudaGetSymbolAddress((void**)&x1,   g_x1);
    cudaGetSymbolAddress((void**)&x2,   g_x2);
    cudaGetSymbolAddress((void**)&ctr,  g_ctx);
    cudaGetSymbolAddress((void**)&ffh,  g_ffh);
    cudaGetSymbolAddress((void**)&part, g_part);
    cudaGetSymbolAddress((void**)&wts,  g_wts);
    cudaGetSymbolAddress((void**)&wtc,  g_wtc);
    cudaGetSymbolAddress((void**)&w1t,  g_w1t);
    cudaGetSymbolAddress((void**)&w2t,  g_w2t);
    cudaGetSymbolAddress((void**)&bqkv, g_bqkv);
    cudaGetSymbolAddress((void**)&bkvc, g_bkvc);

    const int SMEM_GEMM = STAGES * TILEWW * 2 * 4;   // 102400 B
    const int SMEM_ATTN = 4 * KTILE_B;               // 36864 B

    static cudaStream_t s1 = nullptr;
    static cudaEvent_t eFork, eW1, eW2, eKV, eW3;
    static bool inited = false;
    if (!inited) {
        cudaStreamCreateWithFlags(&s1, cudaStreamNonBlocking);
        cudaEventCreateWithFlags(&eFork, cudaEventDisableTiming);
        cudaEventCreateWithFlags(&eW1,   cudaEventDisableTiming);
        cudaEventCreateWithFlags(&eW2,   cudaEventDisableTiming);
        cudaEventCreateWithFlags(&eKV,   cudaEventDisableTiming);
        cudaEventCreateWithFlags(&eW3,   cudaEventDisableTiming);
        cudaFuncSetAttribute(gemm_mma<0, false, true,  1>, cudaFuncAttributeMaxDynamicSharedMemorySize, SMEM_GEMM);
        cudaFuncSetAttribute(gemm_mma<1, false, true,  1>, cudaFuncAttributeMaxDynamicSharedMemorySize, SMEM_GEMM);
        cudaFuncSetAttribute(gemm_mma<0, false, false, 2>, cudaFuncAttributeMaxDynamicSharedMemorySize, SMEM_GEMM);
        cudaFuncSetAttribute(attn_tc, cudaFuncAttributeMaxDynamicSharedMemorySize, SMEM_ATTN);
        inited = true;
    }

    dim3 gqkv (3 * D / 128, MQ / 128);       // (18, 64)
    dim3 gq   (D / 128, MQ / 128);           // (6, 64)
    dim3 gkvc (2 * D / 128, MKV / 128);      // (12, 16)
    dim3 gff1 (FFD / 128, MQ / 128);         // (24, 64)
    dim3 gff2 (D / 128, MQ / 128, 2);        // (6, 64, 2) split-K

    // ---- fork side stream (all input-only work) ----
    cudaEventRecord(eFork, 0);
    cudaStreamWaitEvent(s1, eFork, 0);

    repack_kernel<<<dim3(HS / 32, D / 32, 3 * HH), dim3(32, 8), 0, s1>>>(sWq, sWk, sWv, wts);
    concat3_kernel<<<9, 256, 0, s1>>>(sbq, sbk, sbv, bqkv);
    cudaEventRecord(eW1, s1);
    round_kernel<<<(MKV * D + 255) / 256, 256, 0, s1>>>(ctx, ctr, MKV * D);
    repack_kernel<<<dim3(HS / 32, D / 32, 3 * HH), dim3(32, 8), 0, s1>>>(cWq, cWk, cWv, wtc);
    concat2_kernel<<<6, 256, 0, s1>>>(cbk, cbv, bkvc);
    cudaEventRecord(eW2, s1);
    gemm_mma<0, false, true, 1><<<gkvc, 256, SMEM_GEMM, s1>>>(ctr, wtc + DD, bkvc, nullptr, kvc, MKV, 2 * D, D);
    cudaEventRecord(eKV, s1);
    transpose_kernel<<<dim3(FFD / 32, D / 32), dim3(32, 8), 0, s1>>>(W1, w1t, D, FFD);
    transpose_kernel<<<dim3(D / 32, FFD / 32), dim3(32, 8), 0, s1>>>(W2, w2t, FFD, D);
    cudaEventRecord(eW3, s1);

    // ---- main stream: block 1 (self attention, fused QKV) ----
    ln_kernel<<<MQ / 8, 256>>>(x0, ln1_w, ln1_b, ln);
    cudaStreamWaitEvent(0, eW1, 0);
    gemm_mma<0, false, true, 1><<<gqkv, 256, SMEM_GEMM>>>(ln, wts, bqkv, nullptr, qkv, MQ, 3 * D, D);
    attn_tc<<<dim3(TT / 128, HH, BB), 256, SMEM_ATTN>>>(qkv, 3 * D, qkv + D, qkv + 2 * D, 3 * D,
                                                        x0, x1, TT, TT);

    // ---- block 2: cross attention ----
    ln_kernel<<<MQ / 8, 256>>>(x1, ln2_w, ln2_b, ln);
    cudaStreamWaitEvent(0, eW2, 0);
    gemm_mma<0, false, true, 1><<<gq, 256, SMEM_GEMM>>>(ln, wtc, cbq, nullptr, q, MQ, D, D);
    cudaStreamWaitEvent(0, eKV, 0);
    attn_tc<<<dim3(TT / 128, HH, BB), 256, SMEM_ATTN>>>(q, D, kvc, kvc + D, 2 * D,
                                                        x1, x2, TT, TCC);

    // ---- block 3: FFN (ff2 split-K=2 + fused reduction) ----
    ln_kernel<<<MQ / 8, 256>>>(x2, ln3_w, ln3_b, ln);
    cudaStreamWaitEvent(0, eW3, 0);
    gemm_mma<1, false, true,  1><<<gff1, 256, SMEM_GEMM>>>(ln,  w1t, b1, nullptr, ffh, MQ, FFD, D);
    gemm_mma<0, false, false, 2><<<gff2, 256, SMEM_GEMM>>>(ffh, w2t, b2, nullptr, part, MQ, D, FFD);
    reduce2_kernel<<<(MQ * D / 4 + 255) / 256, 256>>>(part, b2, x2, outp);
}

// round 11
// speedup vs baseline: 1.1226x; 1.1226x over previous
#include <cuda_runtime.h>
#include <cuda_fp16.h>
#include <math.h>
#include <stdint.h>

#define D   768
#define HH  12
#define HS  64
#define BB  8
#define TT  1024
#define TCC 256
#define FFD 3072
#define MQ  (BB*TT)    // 8192 rows
#define MKV (BB*TCC)   // 2048 rows
#define DD  (D*D)

// ---------------- scratch (device globals; no allocs allowed) ----------------
__device__ __half g_ln [MQ*D];
__device__ __half g_q  [MQ*D];                 // cross-attn Q
__device__ __half g_qkv[(size_t)MQ*3*D];       // self-attn fused QKV [8192 x 2304]
__device__ __half g_kvc[(size_t)MKV*2*D];      // cross-attn fused KV [2048 x 1536]
__device__ float  g_x1 [MQ*D];
__device__ float  g_x2 [MQ*D];
__device__ __half g_ctx[MKV*D];                // fp16 context
__device__ __half g_ffh[(size_t)MQ*FFD];
__device__ __half g_wts[3*DD];                 // repacked self QKV weights [2304 x 768] k-major
__device__ __half g_wtc[3*DD];                 // repacked cross QKV weights
__device__ __half g_w1t[(size_t)FFD*D];        // W1^T : [FF, D]
__device__ __half g_w2t[(size_t)D*FFD];        // W2^T : [D, FF]
__device__ float  g_bqkv[3*D];
__device__ float  g_bkvc[2*D];

// ---------------- helpers ----------------
__device__ __forceinline__ uint32_t smem_u32(const void* p) {
    uint32_t a;
    asm("{ .reg .u64 t; cvta.to.shared.u64 t, %1; cvt.u32.u64 %0, t; }" : "=r"(a) : "l"(p));
    return a;
}
__device__ __forceinline__ void cp_async16(uint32_t dst, const void* src) {
    asm volatile("cp.async.cg.shared.global [%0], [%1], 16;" :: "r"(dst), "l"(src));
}
__device__ __forceinline__ void cp_commit() { asm volatile("cp.async.commit_group;"); }
template<int N> __device__ __forceinline__ void cp_wait() {
    asm volatile("cp.async.wait_group %0;" :: "n"(N));
}
__device__ __forceinline__ void mma_f16(float* c, const uint32_t* a, const uint32_t* b) {
    asm volatile("mma.sync.aligned.m16n8k16.row.col.f32.f16.f16.f32 "
        "{%0,%1,%2,%3}, {%4,%5,%6,%7}, {%8,%9}, {%0,%1,%2,%3};"
        : "+f"(c[0]), "+f"(c[1]), "+f"(c[2]), "+f"(c[3])
        : "r"(a[0]), "r"(a[1]), "r"(a[2]), "r"(a[3]), "r"(b[0]), "r"(b[1]));
}
__device__ __forceinline__ void ldm_x4(uint32_t& r0, uint32_t& r1, uint32_t& r2, uint32_t& r3, uint32_t a) {
    asm volatile("ldmatrix.sync.aligned.m8n8.x4.shared.b16 {%0,%1,%2,%3}, [%4];"
        : "=r"(r0), "=r"(r1), "=r"(r2), "=r"(r3) : "r"(a));
}
__device__ __forceinline__ void ldm_x4t(uint32_t& r0, uint32_t& r1, uint32_t& r2, uint32_t& r3, uint32_t a) {
    asm volatile("ldmatrix.sync.aligned.m8n8.x4.trans.shared.b16 {%0,%1,%2,%3}, [%4];"
        : "=r"(r0), "=r"(r1), "=r"(r2), "=r"(r3) : "r"(a));
}
__device__ __forceinline__ uint32_t packh2(float x, float y) {
    __half2 h = __floats2half2_rn(x, y);
    return *(uint32_t*)&h;
}
__device__ __forceinline__ uint32_t ex2h2(uint32_t x) {
    uint32_t r; asm("ex2.approx.f16x2 %0, %1;" : "=r"(r) : "r"(x));
    return r;
}
__device__ __forceinline__ float silu_f(float z) { return z / (1.0f + expf(-z)); }

// ---------------- LayerNorm: warp-per-row, no smem, fp16 out ----------------
__global__ void ln_kernel(const float* __restrict__ x, const float* __restrict__ w,
                          const float* __restrict__ b, __half* __restrict__ out) {
    int lane = threadIdx.x & 31, wrp = threadIdx.x >> 5;
    int row = blockIdx.x * 8 + wrp;
    const float* xr = x + (size_t)row * D;

    float4 v[6];
    float s = 0.0f, sq = 0.0f;
    #pragma unroll
    for (int j = 0; j < 6; j++) {
        v[j] = *(const float4*)(xr + lane * 4 + j * 128);
        s  += (v[j].x + v[j].y) + (v[j].z + v[j].w);
        sq += v[j].x*v[j].x + v[j].y*v[j].y + v[j].z*v[j].z + v[j].w*v[j].w;
    }
    #pragma unroll
    for (int o = 16; o; o >>= 1) {
        s  += __shfl_xor_sync(0xffffffffu, s,  o);
        sq += __shfl_xor_sync(0xffffffffu, sq, o);
    }
    float mu  = s * (1.0f / D);
    float inv = rsqrtf(sq * (1.0f / D) - mu * mu + 1e-5f);

    __half* orow = out + (size_t)row * D;
    #pragma unroll
    for (int j = 0; j < 6; j++) {
        int c = lane * 4 + j * 128;
        float4 wv = *(const float4*)(w + c);
        float4 bv = *(const float4*)(b + c);
        __half2 h0 = __floats2half2_rn((v[j].x - mu) * inv * wv.x + bv.x,
                                       (v[j].y - mu) * inv * wv.y + bv.y);
        __half2 h1 = __floats2half2_rn((v[j].z - mu) * inv * wv.z + bv.z,
                                       (v[j].w - mu) * inv * wv.w + bv.w);
        uint2 pk = make_uint2(*(uint32_t*)&h0, *(uint32_t*)&h1);
        *(uint2*)(orow + c) = pk;
    }
}

// ------------- repack [H,D,HS] QKV weights -> [N rows, K] k-major fp16 (coalesced) -------------
__global__ void repack_kernel(const float* __restrict__ Wq, const float* __restrict__ Wk,
                              const float* __restrict__ Wv, __half* __restrict__ dst) {
    __shared__ float tile[32][33];
    int m = blockIdx.z / HH, h = blockIdx.z % HH;
    const float* W = (m == 0) ? Wq : ((m == 1) ? Wk : Wv);
    const float* Wh = W + (size_t)h * D * HS;
    int e0 = blockIdx.x * 32, d0 = blockIdx.y * 32;
    #pragma unroll
    for (int i = 0; i < 32; i += 8)
        tile[threadIdx.y + i][threadIdx.x] = Wh[(size_t)(d0 + threadIdx.y + i) * HS + e0 + threadIdx.x];
    __syncthreads();
    __half* dm = dst + (size_t)m * DD;
    #pragma unroll
    for (int i = 0; i < 32; i += 8)
        dm[(size_t)(h * HS + e0 + threadIdx.y + i) * D + d0 + threadIdx.x] =
            __float2half_rn(tile[threadIdx.x][threadIdx.y + i]);
}

// ------------- tiled transpose + fp16 convert -------------
__global__ void transpose_kernel(const float* __restrict__ src, __half* __restrict__ dst,
                                 int R, int C) {
    __shared__ float tile[32][33];
    int bx = blockIdx.x * 32, by = blockIdx.y * 32;
    int x = bx + threadIdx.x;
    #pragma unroll
    for (int i = 0; i < 32; i += 8)
        tile[threadIdx.y + i][threadIdx.x] = src[(size_t)(by + threadIdx.y + i) * C + x];
    __syncthreads();
    int x2 = by + threadIdx.x;
    #pragma unroll
    for (int i = 0; i < 32; i += 8)
        dst[(size_t)(bx + threadIdx.y + i) * R + x2] = __float2half_rn(tile[threadIdx.x][threadIdx.y + i]);
}

__global__ void round_kernel(const float* __restrict__ src, __half* __restrict__ dst, int n) {
    int i = blockIdx.x * blockDim.x + threadIdx.x;
    if (i < n) dst[i] = __float2half_rn(src[i]);
}
__global__ void concat3_kernel(const float* __restrict__ a, const float* __restrict__ b,
                               const float* __restrict__ c, float* __restrict__ dst) {
    int i = blockIdx.x * blockDim.x + threadIdx.x;
    if (i < D) dst[i] = a[i];
    else if (i < 2 * D) dst[i] = b[i - D];
    else if (i < 3 * D) dst[i] = c[i - 2 * D];
}
__global__ void concat2_kernel(const float* __restrict__ a, const float* __restrict__ b,
                               float* __restrict__ dst) {
    int i = blockIdx.x * blockDim.x + threadIdx.x;
    if (i < D) dst[i] = a[i];
    else if (i < 2 * D) dst[i] = b[i - D];
}

// =======================================================================================
// fp16 mma.sync GEMM: BM=BN=128, BK=32, 256 threads, 4-stage cp.async, ldmatrix frags.
// =======================================================================================
#define WS     20
#define STAGES 4
#define TILEWW (128 * WS)

template<int ACT, bool RES, bool OUTH>
__global__ __launch_bounds__(256)
void gemm_mma(const __half* __restrict__ A, const __half* __restrict__ Bt,
              const float* __restrict__ bias, const float* __restrict__ res,
              void* __restrict__ Cv, int M, int N, int K) {
    extern __shared__ uint32_t smw[];

    const int tid  = threadIdx.x;
    const int lane = tid & 31, wid = tid >> 5;
    const int warp_m = wid & 1, warp_n = wid >> 1;
    const int bm = blockIdx.y * 128, bn = blockIdx.x * 128;
    const uint32_t sbase = smem_u32(smw);

    const int r0l = tid >> 2, subl = tid & 3;
    const __half* Ag = A + (size_t)(bm + r0l) * K + subl * 8;
    const __half* Bg = Bt + (size_t)(bn + r0l) * K + subl * 8;
    const uint32_t adst0 = sbase + (uint32_t)(r0l * WS + subl * 4) * 4u;
    const uint32_t bdst0 = sbase + (uint32_t)(STAGES * TILEWW + r0l * WS + subl * 4) * 4u;

    const int nt = K >> 5;

    auto prefetch = [&](int kt) {
        int s = kt % STAGES;
        uint32_t ad = adst0 + (uint32_t)(s * TILEWW) * 4u;
        uint32_t bd = bdst0 + (uint32_t)(s * TILEWW) * 4u;
        const __half* ag = Ag + kt * 32;
        const __half* bg = Bg + kt * 32;
        cp_async16(ad, ag);
        cp_async16(ad + (uint32_t)(64 * WS) * 4u, ag + (size_t)64 * K);
        cp_async16(bd, bg);
        cp_async16(bd + (uint32_t)(64 * WS) * 4u, bg + (size_t)64 * K);
    };

    float acc[4][4][4];
    #pragma unroll
    for (int mi = 0; mi < 4; mi++)
        #pragma unroll
        for (int ni = 0; ni < 4; ni++)
            #pragma unroll
            for (int e = 0; e < 4; e++) acc[mi][ni][e] = 0.0f;

    #pragma unroll
    for (int s = 0; s < STAGES - 1; s++) { prefetch(s); cp_commit(); }

    const uint32_t a_l = (uint32_t)((warp_m * 64 + (lane & 15)) * WS) * 4u + (uint32_t)((lane >> 4) * 16);
    const uint32_t b_l = (uint32_t)(STAGES * TILEWW) * 4u +
                         (uint32_t)((warp_n * 32 + (lane & 7) + ((lane >> 4) << 3)) * WS) * 4u +
                         (uint32_t)(((lane >> 3) & 1) * 16);

    for (int kt = 0; kt < nt; kt++) {
        cp_wait<STAGES - 2>();
        __syncthreads();
        if (kt + STAGES - 1 < nt) prefetch(kt + STAGES - 1);
        cp_commit();

        int s = kt % STAGES;
        const uint32_t soff = (uint32_t)(s * TILEWW) * 4u;
        const uint32_t abase_s = sbase + soff + a_l;
        const uint32_t bbase_s = sbase + soff + b_l;

        #pragma unroll
        for (int ks = 0; ks < 2; ks++) {
            const uint32_t koff = (uint32_t)(ks * 32);
            uint32_t af[4][4], bf[4][2];
            #pragma unroll
            for (int mi = 0; mi < 4; mi++)
                ldm_x4(af[mi][0], af[mi][1], af[mi][2], af[mi][3],
                       abase_s + (uint32_t)(mi * 16 * WS) * 4u + koff);
            ldm_x4(bf[0][0], bf[0][1], bf[1][0], bf[1][1], bbase_s + koff);
            ldm_x4(bf[2][0], bf[2][1], bf[3][0], bf[3][1],
                   bbase_s + (uint32_t)(16 * WS) * 4u + koff);
            #pragma unroll
            for (int mi = 0; mi < 4; mi++)
                #pragma unroll
                for (int ni = 0; ni < 4; ni++)
                    mma_f16(acc[mi][ni], af[mi], bf[ni]);
        }
    }

    const int lr = lane >> 2, lc = lane & 3;
    #pragma unroll
    for (int mi = 0; mi < 4; mi++) {
        int r0 = bm + warp_m * 64 + mi * 16 + lr;
        #pragma unroll
        for (int ni = 0; ni < 4; ni++) {
            int c0 = bn + warp_n * 32 + ni * 8 + 2 * lc;
            float b0 = bias[c0], b1 = bias[c0 + 1];
            float v00 = acc[mi][ni][0] + b0, v01 = acc[mi][ni][1] + b1;
            float v10 = acc[mi][ni][2] + b0, v11 = acc[mi][ni][3] + b1;
            if (ACT == 1) { v00 = silu_f(v00); v01 = silu_f(v01); v10 = silu_f(v10); v11 = silu_f(v11); }
            if (RES) {
                const float2 rA = *(const float2*)(res + (size_t)r0 * N + c0);
                const float2 rB = *(const float2*)(res + (size_t)(r0 + 8) * N + c0);
                v00 += rA.x; v01 += rA.y; v10 += rB.x; v11 += rB.y;
            }
            if (OUTH) {
                __half* Ch = (__half*)Cv;
                uint32_t p0 = packh2(v00, v01), p1 = packh2(v10, v11);
                *(uint32_t*)(Ch + (size_t)r0 * N + c0)       = p0;
                *(uint32_t*)(Ch + (size_t)(r0 + 8) * N + c0) = p1;
            } else {
                float* Cf = (float*)Cv;
                *(float2*)(Cf + (size_t)r0 * N + c0)       = make_float2(v00, v01);
                *(float2*)(Cf + (size_t)(r0 + 8) * N + c0) = make_float2(v10, v11);
            }
        }
    }
}

// =======================================================================================
// fp16 tensor-core flash attention: f16x2 exp2 + ones-MMA row sums.
// =======================================================================================
#define KVSTR_B 144
#define KTILE_B (64 * KVSTR_B)
#define ONESH2  0x3C003C00u

__global__ __launch_bounds__(256)
void attn_tc(const __half* __restrict__ Q, int ldq,
             const __half* __restrict__ Kg, const __half* __restrict__ Vg, int ldkv,
             const float* __restrict__ xres, float* __restrict__ out,
             int Tq, int Tkv) {
    extern __shared__ uint32_t smw[];
    const uint32_t sbase = smem_u32(smw);

    const int tid = threadIdx.x;
    const int lane = tid & 31, wid = tid >> 5;
    const int lr = lane >> 2, lc = lane & 3;
    const int h = blockIdx.y, b = blockIdx.z;
    const int brow = b * Tq + blockIdx.x * 128;
    const int m0 = wid * 16;

    const __half* Kb = Kg + (size_t)b * Tkv * ldkv + h * HS;
    const __half* Vb = Vg + (size_t)b * Tkv * ldkv + h * HS;

    const float SC2 = 0.125f * 1.4426950408889634f;
    uint32_t qf[4][4];
    {
        const __half* Qp = Q + (size_t)(brow + m0) * ldq + h * HS;
        #pragma unroll
        for (int ks = 0; ks < 4; ks++) {
            int c = ks * 16 + 2 * lc;
            #pragma unroll
            for (int e = 0; e < 4; e++) {
                int rr = (e & 1) ? lr + 8 : lr;
                int cc = c + ((e >> 1) ? 8 : 0);
                __half2 hv = *(const __half2*)(Qp + (size_t)rr * ldq + cc);
                float2 f = __half22float2(hv);
                qf[ks][e] = packh2(f.x * SC2, f.y * SC2);
            }
        }
    }

    const int rl = lane & 7;
    const uint32_t loff_k = (uint32_t)(rl * KVSTR_B + ((lane >> 3) * 16));
    const uint32_t loff_v = (uint32_t)(((((lane >> 3) & 1) * 8 + rl) * KVSTR_B) + ((lane >> 4) * 16));

    const int lrow = tid >> 3, lsub = tid & 7;
    auto prefetch = [&](int kt) {
        int buf = kt & 1;
        uint32_t kdst = sbase + buf * KTILE_B + lrow * KVSTR_B + lsub * 16;
        uint32_t vdst = kdst + 2 * KTILE_B;
        const __half* kp = Kb + (size_t)(kt * 64 + lrow) * ldkv + lsub * 8;
        const __half* vp = Vb + (size_t)(kt * 64 + lrow) * ldkv + lsub * 8;
        cp_async16(kdst, kp);
        cp_async16(kdst + 32 * KVSTR_B, kp + (size_t)32 * ldkv);
        cp_async16(vdst, vp);
        cp_async16(vdst + 32 * KVSTR_B, vp + (size_t)32 * ldkv);
    };

    float oacc[8][4];
    #pragma unroll
    for (int i = 0; i < 8; i++)
        #pragma unroll
        for (int e = 0; e < 4; e++) oacc[i][e] = 0.0f;
    float lacc[4] = {0.0f, 0.0f, 0.0f, 0.0f};
    float mstate0 = -1e30f, mstate1 = -1e30f;

    const int nt = Tkv >> 6;
    prefetch(0); cp_commit();

    for (int kt = 0; kt < nt; kt++) {
        if (kt + 1 < nt) { prefetch(kt + 1); cp_commit(); cp_wait<1>(); }
        else             { cp_wait<0>(); }
        __syncthreads();

        const uint32_t kbase = sbase + (kt & 1) * KTILE_B;
        const uint32_t vbase = kbase + 2 * KTILE_B;

        float sacc[8][4];
        #pragma unroll
        for (int nf = 0; nf < 8; nf++)
            #pragma unroll
            for (int e = 0; e < 4; e++) sacc[nf][e] = 0.0f;

        #pragma unroll
        for (int nf = 0; nf < 8; nf++) {
            uint32_t k0, k1, k2, k3, k4, k5, k6, k7;
            uint32_t base = kbase + nf * (8 * KVSTR_B) + loff_k;
            ldm_x4(k0, k1, k2, k3, base);
            ldm_x4(k4, k5, k6, k7, base + 64);
            uint32_t bf[2];
            bf[0] = k0; bf[1] = k1; mma_f16(sacc[nf], qf[0], bf);
            bf[0] = k2; bf[1] = k3; mma_f16(sacc[nf], qf[1], bf);
            bf[0] = k4; bf[1] = k5; mma_f16(sacc[nf], qf[2], bf);
            bf[0] = k6; bf[1] = k7; mma_f16(sacc[nf], qf[3], bf);
        }

        float mx0 = -1e30f, mx1 = -1e30f;
        #pragma unroll
        for (int nf = 0; nf < 8; nf++) {
            mx0 = fmaxf(mx0, fmaxf(sacc[nf][0], sacc[nf][1]));
            mx1 = fmaxf(mx1, fmaxf(sacc[nf][2], sacc[nf][3]));
        }
        mx0 = fmaxf(mx0, __shfl_xor_sync(0xffffffffu, mx0, 1));
        mx0 = fmaxf(mx0, __shfl_xor_sync(0xffffffffu, mx0, 2));
        mx1 = fmaxf(mx1, __shfl_xor_sync(0xffffffffu, mx1, 1));
        mx1 = fmaxf(mx1, __shfl_xor_sync(0xffffffffu, mx1, 2));
        float mn0 = fmaxf(mstate0, mx0), mn1 = fmaxf(mstate1, mx1);
        float corr0 = exp2f(mstate0 - mn0), corr1 = exp2f(mstate1 - mn1);
        mstate0 = mn0; mstate1 = mn1;

        uint32_t pf[8][2];
        #pragma unroll
        for (int nf = 0; nf < 8; nf++) {
            pf[nf][0] = ex2h2(packh2(sacc[nf][0] - mn0, sacc[nf][1] - mn0));
            pf[nf][1] = ex2h2(packh2(sacc[nf][2] - mn1, sacc[nf][3] - mn1));
        }

        #pragma unroll
        for (int nf = 0; nf < 8; nf++) {
            oacc[nf][0] *= corr0; oacc[nf][1] *= corr0;
            oacc[nf][2] *= corr1; oacc[nf][3] *= corr1;
        }
        lacc[0] *= corr0; lacc[1] *= corr0; lacc[2] *= corr1; lacc[3] *= corr1;

        const uint32_t onesf[2] = {ONESH2, ONESH2};
        #pragma unroll
        for (int kg = 0; kg < 4; kg++) {
            uint32_t af[4];
            af[0] = pf[2*kg][0];
            af[1] = pf[2*kg][1];
            af[2] = pf[2*kg+1][0];
            af[3] = pf[2*kg+1][1];
            mma_f16(lacc, af, onesf);
            #pragma unroll
            for (int nfp = 0; nfp < 4; nfp++) {
                uint32_t v0, v1, v2, v3;
                ldm_x4t(v0, v1, v2, v3, vbase + kg * (16 * KVSTR_B) + nfp * 32 + loff_v);
                uint32_t bf[2];
                bf[0] = v0; bf[1] = v1; mma_f16(oacc[2*nfp],     af, bf);
                bf[0] = v2; bf[1] = v3; mma_f16(oacc[2*nfp + 1], af, bf);
            }
        }
        __syncthreads();
    }

    float inv0 = 1.0f / lacc[0], inv1 = 1.0f / lacc[2];
    int row0 = brow + m0 + lr, row1 = row0 + 8;
    #pragma unroll
    for (int nf = 0; nf < 8; nf++) {
        int col = h * HS + nf * 8 + 2 * lc;
        float2 rA = *(const float2*)(xres + (size_t)row0 * D + col);
        float2 rB = *(const float2*)(xres + (size_t)row1 * D + col);
        *(float2*)(out + (size_t)row0 * D + col) =
            make_float2(rA.x + oacc[nf][0] * inv0, rA.y + oacc[nf][1] * inv0);
        *(float2*)(out + (size_t)row1 * D + col) =
            make_float2(rB.x + oacc[nf][2] * inv1, rB.y + oacc[nf][3] * inv1);
    }
}

// ---------------- host launch (multi-stream overlap inside the graph) ----------------
extern "C" void kernel_launch(void* const* d_in, const int* in_sizes, int n_in,
                              void* d_out, int out_size) {
    const float* x0    = (const float*)d_in[0];
    const float* ctx   = (const float*)d_in[1];
    const float* ln1_w = (const float*)d_in[2];
    const float* ln1_b = (const float*)d_in[3];
    const float* sWq   = (const float*)d_in[4];
    const float* sbq   = (const float*)d_in[5];
    const float* sWk   = (const float*)d_in[6];
    const float* sbk   = (const float*)d_in[7];
    const float* sWv   = (const float*)d_in[8];
    const float* sbv   = (const float*)d_in[9];
    const float* ln2_w = (const float*)d_in[10];
    const float* ln2_b = (const float*)d_in[11];
    const float* cWq   = (const float*)d_in[12];
    const float* cbq   = (const float*)d_in[13];
    const float* cWk   = (const float*)d_in[14];
    const float* cbk   = (const float*)d_in[15];
    const float* cWv   = (const float*)d_in[16];
    const float* cbv   = (const float*)d_in[17];
    const float* ln3_w = (const float*)d_in[18];
    const float* ln3_b = (const float*)d_in[19];
    const float* W1    = (const float*)d_in[20];
    const float* b1    = (const float*)d_in[21];
    const float* W2    = (const float*)d_in[22];
    const float* b2    = (const float*)d_in[23];
    float* outp = (float*)d_out;

    __half *ln, *q, *qkv, *kvc, *ctr, *ffh, *wts, *wtc, *w1t, *w2t;
    float *x1, *x2, *bqkv, *bkvc;
    cudaGetSymbolAddress((void**)&ln,   g_ln);
    cudaGetSymbolAddress((void**)&q,    g_q);
    cudaGetSymbolAddress((void**)&qkv,  g_qkv);
    cudaGetSymbolAddress((void**)&kvc,  g_kvc);
    cudaGetSymbolAddress((void**)&x1,   g_x1);
    cudaGetSymbolAddress((void**)&x2,   g_x2);
    cudaGetSymbolAddress((void**)&ctr,  g_ctx);
    cudaGetSymbolAddress((void**)&ffh,  g_ffh);
    cudaGetSymbolAddress((void**)&wts,  g_wts);
    cudaGetSymbolAddress((void**)&wtc,  g_wtc);
    cudaGetSymbolAddress((void**)&w1t,  g_w1t);
    cudaGetSymbolAddress((void**)&w2t,  g_w2t);
    cudaGetSymbolAddress((void**)&bqkv, g_bqkv);
    cudaGetSymbolAddress((void**)&bkvc, g_bkvc);

    const int SMEM_GEMM = STAGES * TILEWW * 2 * 4;   // 81920 B
    const int SMEM_ATTN = 4 * KTILE_B;               // 36864 B

    static cudaStream_t s1 = nullptr;
    static cudaEvent_t eFork, eW1, eW2, eKV, eW3;
    static bool inited = false;
    if (!inited) {
        cudaStreamCreateWithFlags(&s1, cudaStreamNonBlocking);
        cudaEventCreateWithFlags(&eFork, cudaEventDisableTiming);
        cudaEventCreateWithFlags(&eW1,   cudaEventDisableTiming);
        cudaEventCreateWithFlags(&eW2,   cudaEventDisableTiming);
        cudaEventCreateWithFlags(&eKV,   cudaEventDisableTiming);
        cudaEventCreateWithFlags(&eW3,   cudaEventDisableTiming);
        cudaFuncSetAttribute(gemm_mma<0, false, true >, cudaFuncAttributeMaxDynamicSharedMemorySize, SMEM_GEMM);
        cudaFuncSetAttribute(gemm_mma<1, false, true >, cudaFuncAttributeMaxDynamicSharedMemorySize, SMEM_GEMM);
        cudaFuncSetAttribute(gemm_mma<0, true,  false>, cudaFuncAttributeMaxDynamicSharedMemorySize, SMEM_GEMM);
        cudaFuncSetAttribute(attn_tc, cudaFuncAttributeMaxDynamicSharedMemorySize, SMEM_ATTN);
        inited = true;
    }

    dim3 gqkv (3 * D / 128, MQ / 128);   // (18, 64)
    dim3 gq   (D / 128, MQ / 128);       // (6, 64)
    dim3 gkvc (2 * D / 128, MKV / 128);  // (12, 16)
    dim3 gff1 (FFD / 128, MQ / 128);     // (24, 64)
    dim3 gff2 (D / 128, MQ / 128);       // (6, 64)

    // ---- fork side stream (all input-only work) ----
    cudaEventRecord(eFork, 0);
    cudaStreamWaitEvent(s1, eFork, 0);

    repack_kernel<<<dim3(HS / 32, D / 32, 3 * HH), dim3(32, 8), 0, s1>>>(sWq, sWk, sWv, wts);
    concat3_kernel<<<9, 256, 0, s1>>>(sbq, sbk, sbv, bqkv);
    cudaEventRecord(eW1, s1);
    round_kernel<<<(MKV * D + 255) / 256, 256, 0, s1>>>(ctx, ctr, MKV * D);
    repack_kernel<<<dim3(HS / 32, D / 32, 3 * HH), dim3(32, 8), 0, s1>>>(cWq, cWk, cWv, wtc);
    concat2_kernel<<<6, 256, 0, s1>>>(cbk, cbv, bkvc);
    cudaEventRecord(eW2, s1);
    gemm_mma<0, false, true><<<gkvc, 256, SMEM_GEMM, s1>>>(ctr, wtc + DD, bkvc, nullptr, kvc, MKV, 2 * D, D);
    cudaEventRecord(eKV, s1);
    transpose_kernel<<<dim3(FFD / 32, D / 32), dim3(32, 8), 0, s1>>>(W1, w1t, D, FFD);
    transpose_kernel<<<dim3(D / 32, FFD / 32), dim3(32, 8), 0, s1>>>(W2, w2t, FFD, D);
    cudaEventRecord(eW3, s1);

    // ---- main stream: block 1 (self attention, fused QKV) ----
    ln_kernel<<<MQ / 8, 256>>>(x0, ln1_w, ln1_b, ln);
    cudaStreamWaitEvent(0, eW1, 0);
    gemm_mma<0, false, true><<<gqkv, 256, SMEM_GEMM>>>(ln, wts, bqkv, nullptr, qkv, MQ, 3 * D, D);
    attn_tc<<<dim3(TT / 128, HH, BB), 256, SMEM_ATTN>>>(qkv, 3 * D, qkv + D, qkv + 2 * D, 3 * D,
                                                        x0, x1, TT, TT);

    // ---- block 2: cross attention ----
    ln_kernel<<<MQ / 8, 256>>>(x1, ln2_w, ln2_b, ln);
    cudaStreamWaitEvent(0, eW2, 0);
    gemm_mma<0, false, true><<<gq, 256, SMEM_GEMM>>>(ln, wtc, cbq, nullptr, q, MQ, D, D);
    cudaStreamWaitEvent(0, eKV, 0);
    attn_tc<<<dim3(TT / 128, HH, BB), 256, SMEM_ATTN>>>(q, D, kvc, kvc + D, 2 * D,
                                                        x1, x2, TT, TCC);

    // ---- block 3: FFN ----
    ln_kernel<<<MQ / 8, 256>>>(x2, ln3_w, ln3_b, ln);
    cudaStreamWaitEvent(0, eW3, 0);
    gemm_mma<1, false, true ><<<gff1, 256, SMEM_GEMM>>>(ln,  w1t, b1, nullptr, ffh,  MQ, FFD, D);
    gemm_mma<0, true,  false><<<gff2, 256, SMEM_GEMM>>>(ffh, w2t, b2, x2,      outp, MQ, D, FFD);
}

// round 12
// speedup vs baseline: 1.1309x; 1.0073x over previous
#include <cuda_runtime.h>
#include <cuda_fp16.h>
#include <math.h>
#include <stdint.h>

#define D   768
#define HH  12
#define HS  64
#define BB  8
#define TT  1024
#define TCC 256
#define FFD 3072
#define MQ  (BB*TT)    // 8192 rows
#define MKV (BB*TCC)   // 2048 rows
#define DD  (D*D)

// ---------------- scratch (device globals; no allocs allowed) ----------------
__device__ __half g_ln [MQ*D];
__device__ __half g_q  [MQ*D];                 // cross-attn Q
__device__ __half g_qkv[(size_t)MQ*3*D];       // self-attn fused QKV [8192 x 2304]
__device__ __half g_kvc[(size_t)MKV*2*D];      // cross-attn fused KV [2048 x 1536]
__device__ float  g_x1 [MQ*D];
__device__ float  g_x2 [MQ*D];
__device__ __half g_ctx[MKV*D];                // fp16 context
__device__ __half g_ffh[(size_t)MQ*FFD];
__device__ __half g_wts[3*DD];                 // repacked self QKV weights [2304 x 768] k-major
__device__ __half g_wtc[3*DD];                 // repacked cross QKV weights
__device__ __half g_w1t[(size_t)FFD*D];        // W1^T : [FF, D]
__device__ __half g_w2t[(size_t)D*FFD];        // W2^T : [D, FF]
__device__ float  g_bqkv[3*D];
__device__ float  g_bkvc[2*D];

// ---------------- helpers ----------------
__device__ __forceinline__ uint32_t smem_u32(const void* p) {
    uint32_t a;
    asm("{ .reg .u64 t; cvta.to.shared.u64 t, %1; cvt.u32.u64 %0, t; }" : "=r"(a) : "l"(p));
    return a;
}
__device__ __forceinline__ void cp_async16(uint32_t dst, const void* src) {
    asm volatile("cp.async.cg.shared.global [%0], [%1], 16;" :: "r"(dst), "l"(src));
}
__device__ __forceinline__ void cp_commit() { asm volatile("cp.async.commit_group;"); }
template<int N> __device__ __forceinline__ void cp_wait() {
    asm volatile("cp.async.wait_group %0;" :: "n"(N));
}
__device__ __forceinline__ void mma_f16(float* c, const uint32_t* a, const uint32_t* b) {
    asm volatile("mma.sync.aligned.m16n8k16.row.col.f32.f16.f16.f32 "
        "{%0,%1,%2,%3}, {%4,%5,%6,%7}, {%8,%9}, {%0,%1,%2,%3};"
        : "+f"(c[0]), "+f"(c[1]), "+f"(c[2]), "+f"(c[3])
        : "r"(a[0]), "r"(a[1]), "r"(a[2]), "r"(a[3]), "r"(b[0]), "r"(b[1]));
}
__device__ __forceinline__ void ldm_x4(uint32_t& r0, uint32_t& r1, uint32_t& r2, uint32_t& r3, uint32_t a) {
    asm volatile("ldmatrix.sync.aligned.m8n8.x4.shared.b16 {%0,%1,%2,%3}, [%4];"
        : "=r"(r0), "=r"(r1), "=r"(r2), "=r"(r3) : "r"(a));
}
__device__ __forceinline__ void ldm_x4t(uint32_t& r0, uint32_t& r1, uint32_t& r2, uint32_t& r3, uint32_t a) {
    asm volatile("ldmatrix.sync.aligned.m8n8.x4.trans.shared.b16 {%0,%1,%2,%3}, [%4];"
        : "=r"(r0), "=r"(r1), "=r"(r2), "=r"(r3) : "r"(a));
}
__device__ __forceinline__ uint32_t packh2(float x, float y) {
    __half2 h = __floats2half2_rn(x, y);
    return *(uint32_t*)&h;
}
__device__ __forceinline__ uint32_t ex2h2(uint32_t x) {
    uint32_t r; asm("ex2.approx.f16x2 %0, %1;" : "=r"(r) : "r"(x));
    return r;
}
// fast SiLU: z * 1/(1 + 2^(-z*log2e)) via MUFU ex2 + rcp (2 MUFU + 2 FMA)
__device__ __forceinline__ float silu_f(float z) {
    float e, r;
    float t = -1.4426950408889634f * z;
    asm("ex2.approx.f32 %0, %1;" : "=f"(e) : "f"(t));
    float d = 1.0f + e;
    asm("rcp.approx.f32 %0, %1;" : "=f"(r) : "f"(d));
    return z * r;
}

// ---------------- LayerNorm: warp-per-row, no smem, fp16 out ----------------
__global__ void ln_kernel(const float* __restrict__ x, const float* __restrict__ w,
                          const float* __restrict__ b, __half* __restrict__ out) {
    int lane = threadIdx.x & 31, wrp = threadIdx.x >> 5;
    int row = blockIdx.x * 8 + wrp;
    const float* xr = x + (size_t)row * D;

    float4 v[6];
    float s = 0.0f, sq = 0.0f;
    #pragma unroll
    for (int j = 0; j < 6; j++) {
        v[j] = *(const float4*)(xr + lane * 4 + j * 128);
        s  += (v[j].x + v[j].y) + (v[j].z + v[j].w);
        sq += v[j].x*v[j].x + v[j].y*v[j].y + v[j].z*v[j].z + v[j].w*v[j].w;
    }
    #pragma unroll
    for (int o = 16; o; o >>= 1) {
        s  += __shfl_xor_sync(0xffffffffu, s,  o);
        sq += __shfl_xor_sync(0xffffffffu, sq, o);
    }
    float mu  = s * (1.0f / D);
    float inv = rsqrtf(sq * (1.0f / D) - mu * mu + 1e-5f);

    __half* orow = out + (size_t)row * D;
    #pragma unroll
    for (int j = 0; j < 6; j++) {
        int c = lane * 4 + j * 128;
        float4 wv = *(const float4*)(w + c);
        float4 bv = *(const float4*)(b + c);
        __half2 h0 = __floats2half2_rn((v[j].x - mu) * inv * wv.x + bv.x,
                                       (v[j].y - mu) * inv * wv.y + bv.y);
        __half2 h1 = __floats2half2_rn((v[j].z - mu) * inv * wv.z + bv.z,
                                       (v[j].w - mu) * inv * wv.w + bv.w);
        uint2 pk = make_uint2(*(uint32_t*)&h0, *(uint32_t*)&h1);
        *(uint2*)(orow + c) = pk;
    }
}

// ------------- repack [H,D,HS] QKV weights -> [N rows, K] k-major fp16 (coalesced) -------------
__global__ void repack_kernel(const float* __restrict__ Wq, const float* __restrict__ Wk,
                              const float* __restrict__ Wv, __half* __restrict__ dst) {
    __shared__ float tile[32][33];
    int m = blockIdx.z / HH, h = blockIdx.z % HH;
    const float* W = (m == 0) ? Wq : ((m == 1) ? Wk : Wv);
    const float* Wh = W + (size_t)h * D * HS;
    int e0 = blockIdx.x * 32, d0 = blockIdx.y * 32;
    #pragma unroll
    for (int i = 0; i < 32; i += 8)
        tile[threadIdx.y + i][threadIdx.x] = Wh[(size_t)(d0 + threadIdx.y + i) * HS + e0 + threadIdx.x];
    __syncthreads();
    __half* dm = dst + (size_t)m * DD;
    #pragma unroll
    for (int i = 0; i < 32; i += 8)
        dm[(size_t)(h * HS + e0 + threadIdx.y + i) * D + d0 + threadIdx.x] =
            __float2half_rn(tile[threadIdx.x][threadIdx.y + i]);
}

// ------------- tiled transpose + fp16 convert -------------
__global__ void transpose_kernel(const float* __restrict__ src, __half* __restrict__ dst,
                                 int R, int C) {
    __shared__ float tile[32][33];
    int bx = blockIdx.x * 32, by = blockIdx.y * 32;
    int x = bx + threadIdx.x;
    #pragma unroll
    for (int i = 0; i < 32; i += 8)
        tile[threadIdx.y + i][threadIdx.x] = src[(size_t)(by + threadIdx.y + i) * C + x];
    __syncthreads();
    int x2 = by + threadIdx.x;
    #pragma unroll
    for (int i = 0; i < 32; i += 8)
        dst[(size_t)(bx + threadIdx.y + i) * R + x2] = __float2half_rn(tile[threadIdx.x][threadIdx.y + i]);
}

__global__ void round_kernel(const float* __restrict__ src, __half* __restrict__ dst, int n) {
    int i = blockIdx.x * blockDim.x + threadIdx.x;
    if (i < n) dst[i] = __float2half_rn(src[i]);
}
__global__ void concat3_kernel(const float* __restrict__ a, const float* __restrict__ b,
                               const float* __restrict__ c, float* __restrict__ dst) {
    int i = blockIdx.x * blockDim.x + threadIdx.x;
    if (i < D) dst[i] = a[i];
    else if (i < 2 * D) dst[i] = b[i - D];
    else if (i < 3 * D) dst[i] = c[i - 2 * D];
}
__global__ void concat2_kernel(const float* __restrict__ a, const float* __restrict__ b,
                               float* __restrict__ dst) {
    int i = blockIdx.x * blockDim.x + threadIdx.x;
    if (i < D) dst[i] = a[i];
    else if (i < 2 * D) dst[i] = b[i - D];
}

// =======================================================================================
// fp16 mma.sync GEMM: BM=BN=128, BK=32, 256 threads, 4-stage cp.async, ldmatrix frags.
// =======================================================================================
#define WS     20
#define STAGES 4
#define TILEWW (128 * WS)

template<int ACT, bool RES, bool OUTH>
__global__ __launch_bounds__(256)
void gemm_mma(const __half* __restrict__ A, const __half* __restrict__ Bt,
              const float* __restrict__ bias, const float* __restrict__ res,
              void* __restrict__ Cv, int M, int N, int K) {
    extern __shared__ uint32_t smw[];

    const int tid  = threadIdx.x;
    const int lane = tid & 31, wid = tid >> 5;
    const int warp_m = wid & 1, warp_n = wid >> 1;
    const int bm = blockIdx.y * 128, bn = blockIdx.x * 128;
    const uint32_t sbase = smem_u32(smw);

    const int r0l = tid >> 2, subl = tid & 3;
    const __half* Ag = A + (size_t)(bm + r0l) * K + subl * 8;
    const __half* Bg = Bt + (size_t)(bn + r0l) * K + subl * 8;
    const uint32_t adst0 = sbase + (uint32_t)(r0l * WS + subl * 4) * 4u;
    const uint32_t bdst0 = sbase + (uint32_t)(STAGES * TILEWW + r0l * WS + subl * 4) * 4u;

    const int nt = K >> 5;

    auto prefetch = [&](int kt) {
        int s = kt % STAGES;
        uint32_t ad = adst0 + (uint32_t)(s * TILEWW) * 4u;
        uint32_t bd = bdst0 + (uint32_t)(s * TILEWW) * 4u;
        const __half* ag = Ag + kt * 32;
        const __half* bg = Bg + kt * 32;
        cp_async16(ad, ag);
        cp_async16(ad + (uint32_t)(64 * WS) * 4u, ag + (size_t)64 * K);
        cp_async16(bd, bg);
        cp_async16(bd + (uint32_t)(64 * WS) * 4u, bg + (size_t)64 * K);
    };

    float acc[4][4][4];
    #pragma unroll
    for (int mi = 0; mi < 4; mi++)
        #pragma unroll
        for (int ni = 0; ni < 4; ni++)
            #pragma unroll
            for (int e = 0; e < 4; e++) acc[mi][ni][e] = 0.0f;

    #pragma unroll
    for (int s = 0; s < STAGES - 1; s++) { prefetch(s); cp_commit(); }

    const uint32_t a_l = (uint32_t)((warp_m * 64 + (lane & 15)) * WS) * 4u + (uint32_t)((lane >> 4) * 16);
    const uint32_t b_l = (uint32_t)(STAGES * TILEWW) * 4u +
                         (uint32_t)((warp_n * 32 + (lane & 7) + ((lane >> 4) << 3)) * WS) * 4u +
                         (uint32_t)(((lane >> 3) & 1) * 16);

    for (int kt = 0; kt < nt; kt++) {
        cp_wait<STAGES - 2>();
        __syncthreads();
        if (kt + STAGES - 1 < nt) prefetch(kt + STAGES - 1);
        cp_commit();

        int s = kt % STAGES;
        const uint32_t soff = (uint32_t)(s * TILEWW) * 4u;
        const uint32_t abase_s = sbase + soff + a_l;
        const uint32_t bbase_s = sbase + soff + b_l;

        #pragma unroll
        for (int ks = 0; ks < 2; ks++) {
            const uint32_t koff = (uint32_t)(ks * 32);
            uint32_t af[4][4], bf[4][2];
            #pragma unroll
            for (int mi = 0; mi < 4; mi++)
                ldm_x4(af[mi][0], af[mi][1], af[mi][2], af[mi][3],
                       abase_s + (uint32_t)(mi * 16 * WS) * 4u + koff);
            ldm_x4(bf[0][0], bf[0][1], bf[1][0], bf[1][1], bbase_s + koff);
            ldm_x4(bf[2][0], bf[2][1], bf[3][0], bf[3][1],
                   bbase_s + (uint32_t)(16 * WS) * 4u + koff);
            #pragma unroll
            for (int mi = 0; mi < 4; mi++)
                #pragma unroll
                for (int ni = 0; ni < 4; ni++)
                    mma_f16(acc[mi][ni], af[mi], bf[ni]);
        }
    }

    const int lr = lane >> 2, lc = lane & 3;
    #pragma unroll
    for (int mi = 0; mi < 4; mi++) {
        int r0 = bm + warp_m * 64 + mi * 16 + lr;
        #pragma unroll
        for (int ni = 0; ni < 4; ni++) {
            int c0 = bn + warp_n * 32 + ni * 8 + 2 * lc;
            float b0 = bias[c0], b1 = bias[c0 + 1];
            float v00 = acc[mi][ni][0] + b0, v01 = acc[mi][ni][1] + b1;
            float v10 = acc[mi][ni][2] + b0, v11 = acc[mi][ni][3] + b1;
            if (ACT == 1) { v00 = silu_f(v00); v01 = silu_f(v01); v10 = silu_f(v10); v11 = silu_f(v11); }
            if (RES) {
                const float2 rA = *(const float2*)(res + (size_t)r0 * N + c0);
                const float2 rB = *(const float2*)(res + (size_t)(r0 + 8) * N + c0);
                v00 += rA.x; v01 += rA.y; v10 += rB.x; v11 += rB.y;
            }
            if (OUTH) {
                __half* Ch = (__half*)Cv;
                uint32_t p0 = packh2(v00, v01), p1 = packh2(v10, v11);
                *(uint32_t*)(Ch + (size_t)r0 * N + c0)       = p0;
                *(uint32_t*)(Ch + (size_t)(r0 + 8) * N + c0) = p1;
            } else {
                float* Cf = (float*)Cv;
                *(float2*)(Cf + (size_t)r0 * N + c0)       = make_float2(v00, v01);
                *(float2*)(Cf + (size_t)(r0 + 8) * N + c0) = make_float2(v10, v11);
            }
        }
    }
}

// =======================================================================================
// fp16 tensor-core flash attention: f16x2 exp2 + ones-MMA row sums.
// =======================================================================================
#define KVSTR_B 144
#define KTILE_B (64 * KVSTR_B)
#define ONESH2  0x3C003C00u

__global__ __launch_bounds__(256)
void attn_tc(const __half* __restrict__ Q, int ldq,
             const __half* __restrict__ Kg, const __half* __restrict__ Vg, int ldkv,
             const float* __restrict__ xres, float* __restrict__ out,
             int Tq, int Tkv) {
    extern __shared__ uint32_t smw[];
    const uint32_t sbase = smem_u32(smw);

    const int tid = threadIdx.x;
    const int lane = tid & 31, wid = tid >> 5;
    const int lr = lane >> 2, lc = lane & 3;
    const int h = blockIdx.y, b = blockIdx.z;
    const int brow = b * Tq + blockIdx.x * 128;
    const int m0 = wid * 16;

    const __half* Kb = Kg + (size_t)b * Tkv * ldkv + h * HS;
    const __half* Vb = Vg + (size_t)b * Tkv * ldkv + h * HS;

    const float SC2 = 0.125f * 1.4426950408889634f;
    uint32_t qf[4][4];
    {
        const __half* Qp = Q + (size_t)(brow + m0) * ldq + h * HS;
        #pragma unroll
        for (int ks = 0; ks < 4; ks++) {
            int c = ks * 16 + 2 * lc;
            #pragma unroll
            for (int e = 0; e < 4; e++) {
                int rr = (e & 1) ? lr + 8 : lr;
                int cc = c + ((e >> 1) ? 8 : 0);
                __half2 hv = *(const __half2*)(Qp + (size_t)rr * ldq + cc);
                float2 f = __half22float2(hv);
                qf[ks][e] = packh2(f.x * SC2, f.y * SC2);
            }
        }
    }

    const int rl = lane & 7;
    const uint32_t loff_k = (uint32_t)(rl * KVSTR_B + ((lane >> 3) * 16));
    const uint32_t loff_v = (uint32_t)(((((lane >> 3) & 1) * 8 + rl) * KVSTR_B) + ((lane >> 4) * 16));

    const int lrow = tid >> 3, lsub = tid & 7;
    auto prefetch = [&](int kt) {
        int buf = kt & 1;
        uint32_t kdst = sbase + buf * KTILE_B + lrow * KVSTR_B + lsub * 16;
        uint32_t vdst = kdst + 2 * KTILE_B;
        const __half* kp = Kb + (size_t)(kt * 64 + lrow) * ldkv + lsub * 8;
        const __half* vp = Vb + (size_t)(kt * 64 + lrow) * ldkv + lsub * 8;
        cp_async16(kdst, kp);
        cp_async16(kdst + 32 * KVSTR_B, kp + (size_t)32 * ldkv);
        cp_async16(vdst, vp);
        cp_async16(vdst + 32 * KVSTR_B, vp + (size_t)32 * ldkv);
    };

    float oacc[8][4];
    #pragma unroll
    for (int i = 0; i < 8; i++)
        #pragma unroll
        for (int e = 0; e < 4; e++) oacc[i][e] = 0.0f;
    float lacc[4] = {0.0f, 0.0f, 0.0f, 0.0f};
    float mstate0 = -1e30f, mstate1 = -1e30f;

    const int nt = Tkv >> 6;
    prefetch(0); cp_commit();

    for (int kt = 0; kt < nt; kt++) {
        if (kt + 1 < nt) { prefetch(kt + 1); cp_commit(); cp_wait<1>(); }
        else             { cp_wait<0>(); }
        __syncthreads();

        const uint32_t kbase = sbase + (kt & 1) * KTILE_B;
        const uint32_t vbase = kbase + 2 * KTILE_B;

        float sacc[8][4];
        #pragma unroll
        for (int nf = 0; nf < 8; nf++)
            #pragma unroll
            for (int e = 0; e < 4; e++) sacc[nf][e] = 0.0f;

        #pragma unroll
        for (int nf = 0; nf < 8; nf++) {
            uint32_t k0, k1, k2, k3, k4, k5, k6, k7;
            uint32_t base = kbase + nf * (8 * KVSTR_B) + loff_k;
            ldm_x4(k0, k1, k2, k3, base);
            ldm_x4(k4, k5, k6, k7, base + 64);
            uint32_t bf[2];
            bf[0] = k0; bf[1] = k1; mma_f16(sacc[nf], qf[0], bf);
            bf[0] = k2; bf[1] = k3; mma_f16(sacc[nf], qf[1], bf);
            bf[0] = k4; bf[1] = k5; mma_f16(sacc[nf], qf[2], bf);
            bf[0] = k6; bf[1] = k7; mma_f16(sacc[nf], qf[3], bf);
        }

        float mx0 = -1e30f, mx1 = -1e30f;
        #pragma unroll
        for (int nf = 0; nf < 8; nf++) {
            mx0 = fmaxf(mx0, fmaxf(sacc[nf][0], sacc[nf][1]));
            mx1 = fmaxf(mx1, fmaxf(sacc[nf][2], sacc[nf][3]));
        }
        mx0 = fmaxf(mx0, __shfl_xor_sync(0xffffffffu, mx0, 1));
        mx0 = fmaxf(mx0, __shfl_xor_sync(0xffffffffu, mx0, 2));
        mx1 = fmaxf(mx1, __shfl_xor_sync(0xffffffffu, mx1, 1));
        mx1 = fmaxf(mx1, __shfl_xor_sync(0xffffffffu, mx1, 2));
        float mn0 = fmaxf(mstate0, mx0), mn1 = fmaxf(mstate1, mx1);
        float corr0 = exp2f(mstate0 - mn0), corr1 = exp2f(mstate1 - mn1);
        mstate0 = mn0; mstate1 = mn1;

        uint32_t pf[8][2];
        #pragma unroll
        for (int nf = 0; nf < 8; nf++) {
            pf[nf][0] = ex2h2(packh2(sacc[nf][0] - mn0, sacc[nf][1] - mn0));
            pf[nf][1] = ex2h2(packh2(sacc[nf][2] - mn1, sacc[nf][3] - mn1));
        }

        #pragma unroll
        for (int nf = 0; nf < 8; nf++) {
            oacc[nf][0] *= corr0; oacc[nf][1] *= corr0;
            oacc[nf][2] *= corr1; oacc[nf][3] *= corr1;
        }
        lacc[0] *= corr0; lacc[1] *= corr0; lacc[2] *= corr1; lacc[3] *= corr1;

        const uint32_t onesf[2] = {ONESH2, ONESH2};
        #pragma unroll
        for (int kg = 0; kg < 4; kg++) {
            uint32_t af[4];
            af[0] = pf[2*kg][0];
            af[1] = pf[2*kg][1];
            af[2] = pf[2*kg+1][0];
            af[3] = pf[2*kg+1][1];
            mma_f16(lacc, af, onesf);
            #pragma unroll
            for (int nfp = 0; nfp < 4; nfp++) {
                uint32_t v0, v1, v2, v3;
                ldm_x4t(v0, v1, v2, v3, vbase + kg * (16 * KVSTR_B) + nfp * 32 + loff_v);
                uint32_t bf[2];
                bf[0] = v0; bf[1] = v1; mma_f16(oacc[2*nfp],     af, bf);
                bf[0] = v2; bf[1] = v3; mma_f16(oacc[2*nfp + 1], af, bf);
            }
        }
        __syncthreads();
    }

    float inv0 = 1.0f / lacc[0], inv1 = 1.0f / lacc[2];
    int row0 = brow + m0 + lr, row1 = row0 + 8;
    #pragma unroll
    for (int nf = 0; nf < 8; nf++) {
        int col = h * HS + nf * 8 + 2 * lc;
        float2 rA = *(const float2*)(xres + (size_t)row0 * D + col);
        float2 rB = *(const float2*)(xres + (size_t)row1 * D + col);
        *(float2*)(out + (size_t)row0 * D + col) =
            make_float2(rA.x + oacc[nf][0] * inv0, rA.y + oacc[nf][1] * inv0);
        *(float2*)(out + (size_t)row1 * D + col) =
            make_float2(rB.x + oacc[nf][2] * inv1, rB.y + oacc[nf][3] * inv1);
    }
}

// ---------------- host launch (multi-stream overlap inside the graph) ----------------
extern "C" void kernel_launch(void* const* d_in, const int* in_sizes, int n_in,
                              void* d_out, int out_size) {
    const float* x0    = (const float*)d_in[0];
    const float* ctx   = (const float*)d_in[1];
    const float* ln1_w = (const float*)d_in[2];
    const float* ln1_b = (const float*)d_in[3];
    const float* sWq   = (const float*)d_in[4];
    const float* sbq   = (const float*)d_in[5];
    const float* sWk   = (const float*)d_in[6];
    const float* sbk   = (const float*)d_in[7];
    const float* sWv   = (const float*)d_in[8];
    const float* sbv   = (const float*)d_in[9];
    const float* ln2_w = (const float*)d_in[10];
    const float* ln2_b = (const float*)d_in[11];
    const float* cWq   = (const float*)d_in[12];
    const float* cbq   = (const float*)d_in[13];
    const float* cWk   = (const float*)d_in[14];
    const float* cbk   = (const float*)d_in[15];
    const float* cWv   = (const float*)d_in[16];
    const float* cbv   = (const float*)d_in[17];
    const float* ln3_w = (const float*)d_in[18];
    const float* ln3_b = (const float*)d_in[19];
    const float* W1    = (const float*)d_in[20];
    const float* b1    = (const float*)d_in[21];
    const float* W2    = (const float*)d_in[22];
    const float* b2    = (const float*)d_in[23];
    float* outp = (float*)d_out;

    __half *ln, *q, *qkv, *kvc, *ctr, *ffh, *wts, *wtc, *w1t, *w2t;
    float *x1, *x2, *bqkv, *bkvc;
    cudaGetSymbolAddress((void**)&ln,   g_ln);
    cudaGetSymbolAddress((void**)&q,    g_q);
    cudaGetSymbolAddress((void**)&qkv,  g_qkv);
    cudaGetSymbolAddress((void**)&kvc,  g_kvc);
    cudaGetSymbolAddress((void**)&x1,   g_x1);
    cudaGetSymbolAddress((void**)&x2,   g_x2);
    cudaGetSymbolAddress((void**)&ctr,  g_ctx);
    cudaGetSymbolAddress((void**)&ffh,  g_ffh);
    cudaGetSymbolAddress((void**)&wts,  g_wts);
    cudaGetSymbolAddress((void**)&wtc,  g_wtc);
    cudaGetSymbolAddress((void**)&w1t,  g_w1t);
    cudaGetSymbolAddress((void**)&w2t,  g_w2t);
    cudaGetSymbolAddress((void**)&bqkv, g_bqkv);
    cudaGetSymbolAddress((void**)&bkvc, g_bkvc);

    const int SMEM_GEMM = STAGES * TILEWW * 2 * 4;   // 81920 B
    const int SMEM_ATTN = 4 * KTILE_B;               // 36864 B

    static cudaStream_t s1 = nullptr;
    static cudaEvent_t eFork, eW1, eW2, eKV, eW3;
    static bool inited = false;
    if (!inited) {
        cudaStreamCreateWithFlags(&s1, cudaStreamNonBlocking);
        cudaEventCreateWithFlags(&eFork, cudaEventDisableTiming);
        cudaEventCreateWithFlags(&eW1,   cudaEventDisableTiming);
        cudaEventCreateWithFlags(&eW2,   cudaEventDisableTiming);
        cudaEventCreateWithFlags(&eKV,   cudaEventDisableTiming);
        cudaEventCreateWithFlags(&eW3,   cudaEventDisableTiming);
        cudaFuncSetAttribute(gemm_mma<0, false, true >, cudaFuncAttributeMaxDynamicSharedMemorySize, SMEM_GEMM);
        cudaFuncSetAttribute(gemm_mma<1, false, true >, cudaFuncAttributeMaxDynamicSharedMemorySize, SMEM_GEMM);
        cudaFuncSetAttribute(gemm_mma<0, true,  false>, cudaFuncAttributeMaxDynamicSharedMemorySize, SMEM_GEMM);
        cudaFuncSetAttribute(attn_tc, cudaFuncAttributeMaxDynamicSharedMemorySize, SMEM_ATTN);
        inited = true;
    }

    dim3 gqkv (3 * D / 128, MQ / 128);   // (18, 64)
    dim3 gq   (D / 128, MQ / 128);       // (6, 64)
    dim3 gkvc (2 * D / 128, MKV / 128);  // (12, 16)
    dim3 gff1 (FFD / 128, MQ / 128);     // (24, 64)
    dim3 gff2 (D / 128, MQ / 128);       // (6, 64)

    // ---- fork side stream (all input-only work) ----
    cudaEventRecord(eFork, 0);
    cudaStreamWaitEvent(s1, eFork, 0);

    repack_kernel<<<dim3(HS / 32, D / 32, 3 * HH), dim3(32, 8), 0, s1>>>(sWq, sWk, sWv, wts);
    concat3_kernel<<<9, 256, 0, s1>>>(sbq, sbk, sbv, bqkv);
    cudaEventRecord(eW1, s1);
    round_kernel<<<(MKV * D + 255) / 256, 256, 0, s1>>>(ctx, ctr, MKV * D);
    repack_kernel<<<dim3(HS / 32, D / 32, 3 * HH), dim3(32, 8), 0, s1>>>(cWq, cWk, cWv, wtc);
    concat2_kernel<<<6, 256, 0, s1>>>(cbk, cbv, bkvc);
    cudaEventRecord(eW2, s1);
    gemm_mma<0, false, true><<<gkvc, 256, SMEM_GEMM, s1>>>(ctr, wtc + DD, bkvc, nullptr, kvc, MKV, 2 * D, D);
    cudaEventRecord(eKV, s1);
    transpose_kernel<<<dim3(FFD / 32, D / 32), dim3(32, 8), 0, s1>>>(W1, w1t, D, FFD);
    transpose_kernel<<<dim3(D / 32, FFD / 32), dim3(32, 8), 0, s1>>>(W2, w2t, FFD, D);
    cudaEventRecord(eW3, s1);

    // ---- main stream: block 1 (self attention, fused QKV) ----
    ln_kernel<<<MQ / 8, 256>>>(x0, ln1_w, ln1_b, ln);
    cudaStreamWaitEvent(0, eW1, 0);
    gemm_mma<0, false, true><<<gqkv, 256, SMEM_GEMM>>>(ln, wts, bqkv, nullptr, qkv, MQ, 3 * D, D);
    attn_tc<<<dim3(TT / 128, HH, BB), 256, SMEM_ATTN>>>(qkv, 3 * D, qkv + D, qkv + 2 * D, 3 * D,
                                                        x0, x1, TT, TT);

    // ---- block 2: cross attention ----
    ln_kernel<<<MQ / 8, 256>>>(x1, ln2_w, ln2_b, ln);
    cudaStreamWaitEvent(0, eW2, 0);
    gemm_mma<0, false, true><<<gq, 256, SMEM_GEMM>>>(ln, wtc, cbq, nullptr, q, MQ, D, D);
    cudaStreamWaitEvent(0, eKV, 0);
    attn_tc<<<dim3(TT / 128, HH, BB), 256, SMEM_ATTN>>>(q, D, kvc, kvc + D, 2 * D,
                                                        x1, x2, TT, TCC);

    // ---- block 3: FFN ----
    ln_kernel<<<MQ / 8, 256>>>(x2, ln3_w, ln3_b, ln);
    cudaStreamWaitEvent(0, eW3, 0);
    gemm_mma<1, false, true ><<<gff1, 256, SMEM_GEMM>>>(ln,  w1t, b1, nullptr, ffh,  MQ, FFD, D);
    gemm_mma<0, true,  false><<<gff2, 256, SMEM_GEMM>>>(ffh, w2t, b2, x2,      outp, MQ, D, FFD);
}

// round 13
// speedup vs baseline: 1.1750x; 1.0391x over previous
#include <cuda_runtime.h>
#include <cuda_fp16.h>
#include <math.h>
#include <stdint.h>

#define D   768
#define HH  12
#define HS  64
#define BB  8
#define TT  1024
#define TCC 256
#define FFD 3072
#define MQ  (BB*TT)    // 8192 rows
#define MKV (BB*TCC)   // 2048 rows
#define DD  (D*D)
#define MH  (MQ/2)     // 4096 row half

// ---------------- scratch (device globals; no allocs allowed) ----------------
__device__ __half g_ln [MQ*D];
__device__ __half g_q  [MQ*D];                 // cross-attn Q
__device__ __half g_qkv[(size_t)MQ*3*D];       // self-attn fused QKV [8192 x 2304]
__device__ __half g_kvc[(size_t)MKV*2*D];      // cross-attn fused KV [2048 x 1536]
__device__ float  g_x1 [MQ*D];
__device__ float  g_x2 [MQ*D];
__device__ __half g_ctx[MKV*D];                // fp16 context
__device__ __half g_ffh[(size_t)MQ*FFD];
__device__ __half g_wts[3*DD];                 // repacked self QKV weights
__device__ __half g_wtc[3*DD];                 // repacked cross QKV weights
__device__ __half g_w1t[(size_t)FFD*D];        // W1^T : [FF, D]
__device__ __half g_w2t[(size_t)D*FFD];        // W2^T : [D, FF]
__device__ float  g_bqkv[3*D];
__device__ float  g_bkvc[2*D];

// ---------------- helpers ----------------
__device__ __forceinline__ uint32_t smem_u32(const void* p) {
    uint32_t a;
    asm("{ .reg .u64 t; cvta.to.shared.u64 t, %1; cvt.u32.u64 %0, t; }" : "=r"(a) : "l"(p));
    return a;
}
__device__ __forceinline__ void cp_async16(uint32_t dst, const void* src) {
    asm volatile("cp.async.cg.shared.global [%0], [%1], 16;" :: "r"(dst), "l"(src));
}
__device__ __forceinline__ void cp_commit() { asm volatile("cp.async.commit_group;"); }
template<int N> __device__ __forceinline__ void cp_wait() {
    asm volatile("cp.async.wait_group %0;" :: "n"(N));
}
__device__ __forceinline__ void mma_f16(float* c, const uint32_t* a, const uint32_t* b) {
    asm volatile("mma.sync.aligned.m16n8k16.row.col.f32.f16.f16.f32 "
        "{%0,%1,%2,%3}, {%4,%5,%6,%7}, {%8,%9}, {%0,%1,%2,%3};"
        : "+f"(c[0]), "+f"(c[1]), "+f"(c[2]), "+f"(c[3])
        : "r"(a[0]), "r"(a[1]), "r"(a[2]), "r"(a[3]), "r"(b[0]), "r"(b[1]));
}
__device__ __forceinline__ void ldm_x4(uint32_t& r0, uint32_t& r1, uint32_t& r2, uint32_t& r3, uint32_t a) {
    asm volatile("ldmatrix.sync.aligned.m8n8.x4.shared.b16 {%0,%1,%2,%3}, [%4];"
        : "=r"(r0), "=r"(r1), "=r"(r2), "=r"(r3) : "r"(a));
}
__device__ __forceinline__ void ldm_x4t(uint32_t& r0, uint32_t& r1, uint32_t& r2, uint32_t& r3, uint32_t a) {
    asm volatile("ldmatrix.sync.aligned.m8n8.x4.trans.shared.b16 {%0,%1,%2,%3}, [%4];"
        : "=r"(r0), "=r"(r1), "=r"(r2), "=r"(r3) : "r"(a));
}
__device__ __forceinline__ uint32_t packh2(float x, float y) {
    __half2 h = __floats2half2_rn(x, y);
    return *(uint32_t*)&h;
}
__device__ __forceinline__ uint32_t ex2h2(uint32_t x) {
    uint32_t r; asm("ex2.approx.f16x2 %0, %1;" : "=r"(r) : "r"(x));
    return r;
}
// fast SiLU via MUFU ex2 + rcp
__device__ __forceinline__ float silu_f(float z) {
    float e, r;
    float t = -1.4426950408889634f * z;
    asm("ex2.approx.f32 %0, %1;" : "=f"(e) : "f"(t));
    float d = 1.0f + e;
    asm("rcp.approx.f32 %0, %1;" : "=f"(r) : "f"(d));
    return z * r;
}

// ---------------- LayerNorm: warp-per-row, no smem, fp16 out ----------------
__global__ void ln_kernel(const float* __restrict__ x, const float* __restrict__ w,
                          const float* __restrict__ b, __half* __restrict__ out) {
    int lane = threadIdx.x & 31, wrp = threadIdx.x >> 5;
    int row = blockIdx.x * 8 + wrp;
    const float* xr = x + (size_t)row * D;

    float4 v[6];
    float s = 0.0f, sq = 0.0f;
    #pragma unroll
    for (int j = 0; j < 6; j++) {
        v[j] = *(const float4*)(xr + lane * 4 + j * 128);
        s  += (v[j].x + v[j].y) + (v[j].z + v[j].w);
        sq += v[j].x*v[j].x + v[j].y*v[j].y + v[j].z*v[j].z + v[j].w*v[j].w;
    }
    #pragma unroll
    for (int o = 16; o; o >>= 1) {
        s  += __shfl_xor_sync(0xffffffffu, s,  o);
        sq += __shfl_xor_sync(0xffffffffu, sq, o);
    }
    float mu  = s * (1.0f / D);
    float inv = rsqrtf(sq * (1.0f / D) - mu * mu + 1e-5f);

    __half* orow = out + (size_t)row * D;
    #pragma unroll
    for (int j = 0; j < 6; j++) {
        int c = lane * 4 + j * 128;
        float4 wv = *(const float4*)(w + c);
        float4 bv = *(const float4*)(b + c);
        __half2 h0 = __floats2half2_rn((v[j].x - mu) * inv * wv.x + bv.x,
                                       (v[j].y - mu) * inv * wv.y + bv.y);
        __half2 h1 = __floats2half2_rn((v[j].z - mu) * inv * wv.z + bv.z,
                                       (v[j].w - mu) * inv * wv.w + bv.w);
        uint2 pk = make_uint2(*(uint32_t*)&h0, *(uint32_t*)&h1);
        *(uint2*)(orow + c) = pk;
    }
}

// ------------- repack [H,D,HS] QKV weights -> [N rows, K] k-major fp16 (coalesced) -------------
__global__ void repack_kernel(const float* __restrict__ Wq, const float* __restrict__ Wk,
                              const float* __restrict__ Wv, __half* __restrict__ dst) {
    __shared__ float tile[32][33];
    int m = blockIdx.z / HH, h = blockIdx.z % HH;
    const float* W = (m == 0) ? Wq : ((m == 1) ? Wk : Wv);
    const float* Wh = W + (size_t)h * D * HS;
    int e0 = blockIdx.x * 32, d0 = blockIdx.y * 32;
    #pragma unroll
    for (int i = 0; i < 32; i += 8)
        tile[threadIdx.y + i][threadIdx.x] = Wh[(size_t)(d0 + threadIdx.y + i) * HS + e0 + threadIdx.x];
    __syncthreads();
    __half* dm = dst + (size_t)m * DD;
    #pragma unroll
    for (int i = 0; i < 32; i += 8)
        dm[(size_t)(h * HS + e0 + threadIdx.y + i) * D + d0 + threadIdx.x] =
            __float2half_rn(tile[threadIdx.x][threadIdx.y + i]);
}

// ------------- tiled transpose + fp16 convert -------------
__global__ void transpose_kernel(const float* __restrict__ src, __half* __restrict__ dst,
                                 int R, int C) {
    __shared__ float tile[32][33];
    int bx = blockIdx.x * 32, by = blockIdx.y * 32;
    int x = bx + threadIdx.x;
    #pragma unroll
    for (int i = 0; i < 32; i += 8)
        tile[threadIdx.y + i][threadIdx.x] = src[(size_t)(by + threadIdx.y + i) * C + x];
    __syncthreads();
    int x2 = by + threadIdx.x;
    #pragma unroll
    for (int i = 0; i < 32; i += 8)
        dst[(size_t)(bx + threadIdx.y + i) * R + x2] = __float2half_rn(tile[threadIdx.x][threadIdx.y + i]);
}

__global__ void round_kernel(const float* __restrict__ src, __half* __restrict__ dst, int n) {
    int i = blockIdx.x * blockDim.x + threadIdx.x;
    if (i < n) dst[i] = __float2half_rn(src[i]);
}
__global__ void concat3_kernel(const float* __restrict__ a, const float* __restrict__ b,
                               const float* __restrict__ c, float* __restrict__ dst) {
    int i = blockIdx.x * blockDim.x + threadIdx.x;
    if (i < D) dst[i] = a[i];
    else if (i < 2 * D) dst[i] = b[i - D];
    else if (i < 3 * D) dst[i] = c[i - 2 * D];
}
__global__ void concat2_kernel(const float* __restrict__ a, const float* __restrict__ b,
                               float* __restrict__ dst) {
    int i = blockIdx.x * blockDim.x + threadIdx.x;
    if (i < D) dst[i] = a[i];
    else if (i < 2 * D) dst[i] = b[i - D];
}

// =======================================================================================
// fp16 mma.sync GEMM: BM=BN=128, BK=32, 256 threads, 4-stage cp.async, ldmatrix frags.
// =======================================================================================
#define WS     20
#define STAGES 4
#define TILEWW (128 * WS)

template<int ACT, bool RES, bool OUTH>
__global__ __launch_bounds__(256)
void gemm_mma(const __half* __restrict__ A, const __half* __restrict__ Bt,
              const float* __restrict__ bias, const float* __restrict__ res,
              void* __restrict__ Cv, int M, int N, int K) {
    extern __shared__ uint32_t smw[];

    const int tid  = threadIdx.x;
    const int lane = tid & 31, wid = tid >> 5;
    const int warp_m = wid & 1, warp_n = wid >> 1;
    const int bm = blockIdx.y * 128, bn = blockIdx.x * 128;
    const uint32_t sbase = smem_u32(smw);

    const int r0l = tid >> 2, subl = tid & 3;
    const __half* Ag = A + (size_t)(bm + r0l) * K + subl * 8;
    const __half* Bg = Bt + (size_t)(bn + r0l) * K + subl * 8;
    const uint32_t adst0 = sbase + (uint32_t)(r0l * WS + subl * 4) * 4u;
    const uint32_t bdst0 = sbase + (uint32_t)(STAGES * TILEWW + r0l * WS + subl * 4) * 4u;

    const int nt = K >> 5;

    auto prefetch = [&](int kt) {
        int s = kt % STAGES;
        uint32_t ad = adst0 + (uint32_t)(s * TILEWW) * 4u;
        uint32_t bd = bdst0 + (uint32_t)(s * TILEWW) * 4u;
        const __half* ag = Ag + kt * 32;
        const __half* bg = Bg + kt * 32;
        cp_async16(ad, ag);
        cp_async16(ad + (uint32_t)(64 * WS) * 4u, ag + (size_t)64 * K);
        cp_async16(bd, bg);
        cp_async16(bd + (uint32_t)(64 * WS) * 4u, bg + (size_t)64 * K);
    };

    float acc[4][4][4];
    #pragma unroll
    for (int mi = 0; mi < 4; mi++)
        #pragma unroll
        for (int ni = 0; ni < 4; ni++)
            #pragma unroll
            for (int e = 0; e < 4; e++) acc[mi][ni][e] = 0.0f;

    #pragma unroll
    for (int s = 0; s < STAGES - 1; s++) { prefetch(s); cp_commit(); }

    const uint32_t a_l = (uint32_t)((warp_m * 64 + (lane & 15)) * WS) * 4u + (uint32_t)((lane >> 4) * 16);
    const uint32_t b_l = (uint32_t)(STAGES * TILEWW) * 4u +
                         (uint32_t)((warp_n * 32 + (lane & 7) + ((lane >> 4) << 3)) * WS) * 4u +
                         (uint32_t)(((lane >> 3) & 1) * 16);

    for (int kt = 0; kt < nt; kt++) {
        cp_wait<STAGES - 2>();
        __syncthreads();
        if (kt + STAGES - 1 < nt) prefetch(kt + STAGES - 1);
        cp_commit();

        int s = kt % STAGES;
        const uint32_t soff = (uint32_t)(s * TILEWW) * 4u;
        const uint32_t abase_s = sbase + soff + a_l;
        const uint32_t bbase_s = sbase + soff + b_l;

        #pragma unroll
        for (int ks = 0; ks < 2; ks++) {
            const uint32_t koff = (uint32_t)(ks * 32);
            uint32_t af[4][4], bf[4][2];
            #pragma unroll
            for (int mi = 0; mi < 4; mi++)
                ldm_x4(af[mi][0], af[mi][1], af[mi][2], af[mi][3],
                       abase_s + (uint32_t)(mi * 16 * WS) * 4u + koff);
            ldm_x4(bf[0][0], bf[0][1], bf[1][0], bf[1][1], bbase_s + koff);
            ldm_x4(bf[2][0], bf[2][1], bf[3][0], bf[3][1],
                   bbase_s + (uint32_t)(16 * WS) * 4u + koff);
            #pragma unroll
            for (int mi = 0; mi < 4; mi++)
                #pragma unroll
                for (int ni = 0; ni < 4; ni++)
                    mma_f16(acc[mi][ni], af[mi], bf[ni]);
        }
    }

    const int lr = lane >> 2, lc = lane & 3;
    #pragma unroll
    for (int mi = 0; mi < 4; mi++) {
        int r0 = bm + warp_m * 64 + mi * 16 + lr;
        #pragma unroll
        for (int ni = 0; ni < 4; ni++) {
            int c0 = bn + warp_n * 32 + ni * 8 + 2 * lc;
            float b0 = bias[c0], b1 = bias[c0 + 1];
            float v00 = acc[mi][ni][0] + b0, v01 = acc[mi][ni][1] + b1;
            float v10 = acc[mi][ni][2] + b0, v11 = acc[mi][ni][3] + b1;
            if (ACT == 1) { v00 = silu_f(v00); v01 = silu_f(v01); v10 = silu_f(v10); v11 = silu_f(v11); }
            if (RES) {
                const float2 rA = *(const float2*)(res + (size_t)r0 * N + c0);
                const float2 rB = *(const float2*)(res + (size_t)(r0 + 8) * N + c0);
                v00 += rA.x; v01 += rA.y; v10 += rB.x; v11 += rB.y;
            }
            if (OUTH) {
                __half* Ch = (__half*)Cv;
                uint32_t p0 = packh2(v00, v01), p1 = packh2(v10, v11);
                *(uint32_t*)(Ch + (size_t)r0 * N + c0)       = p0;
                *(uint32_t*)(Ch + (size_t)(r0 + 8) * N + c0) = p1;
            } else {
                float* Cf = (float*)Cv;
                *(float2*)(Cf + (size_t)r0 * N + c0)       = make_float2(v00, v01);
                *(float2*)(Cf + (size_t)(r0 + 8) * N + c0) = make_float2(v10, v11);
            }
        }
    }
}

// =======================================================================================
// fp16 tensor-core flash attention: f16x2 exp2 + ones-MMA row sums.
// =======================================================================================
#define KVSTR_B 144
#define KTILE_B (64 * KVSTR_B)
#define ONESH2  0x3C003C00u

__global__ __launch_bounds__(256)
void attn_tc(const __half* __restrict__ Q, int ldq,
             const __half* __restrict__ Kg, const __half* __restrict__ Vg, int ldkv,
             const float* __restrict__ xres, float* __restrict__ out,
             int Tq, int Tkv) {
    extern __shared__ uint32_t smw[];
    const uint32_t sbase = smem_u32(smw);

    const int tid = threadIdx.x;
    const int lane = tid & 31, wid = tid >> 5;
    const int lr = lane >> 2, lc = lane & 3;
    const int h = blockIdx.y, b = blockIdx.z;
    const int brow = b * Tq + blockIdx.x * 128;
    const int m0 = wid * 16;

    const __half* Kb = Kg + (size_t)b * Tkv * ldkv + h * HS;
    const __half* Vb = Vg + (size_t)b * Tkv * ldkv + h * HS;

    const float SC2 = 0.125f * 1.4426950408889634f;
    uint32_t qf[4][4];
    {
        const __half* Qp = Q + (size_t)(brow + m0) * ldq + h * HS;
        #pragma unroll
        for (int ks = 0; ks < 4; ks++) {
            int c = ks * 16 + 2 * lc;
            #pragma unroll
            for (int e = 0; e < 4; e++) {
                int rr = (e & 1) ? lr + 8 : lr;
                int cc = c + ((e >> 1) ? 8 : 0);
                __half2 hv = *(const __half2*)(Qp + (size_t)rr * ldq + cc);
                float2 f = __half22float2(hv);
                qf[ks][e] = packh2(f.x * SC2, f.y * SC2);
            }
        }
    }

    const int rl = lane & 7;
    const uint32_t loff_k = (uint32_t)(rl * KVSTR_B + ((lane >> 3) * 16));
    const uint32_t loff_v = (uint32_t)(((((lane >> 3) & 1) * 8 + rl) * KVSTR_B) + ((lane >> 4) * 16));

    const int lrow = tid >> 3, lsub = tid & 7;
    auto prefetch = [&](int kt) {
        int buf = kt & 1;
        uint32_t kdst = sbase + buf * KTILE_B + lrow * KVSTR_B + lsub * 16;
        uint32_t vdst = kdst + 2 * KTILE_B;
        const __half* kp = Kb + (size_t)(kt * 64 + lrow) * ldkv + lsub * 8;
        const __half* vp = Vb + (size_t)(kt * 64 + lrow) * ldkv + lsub * 8;
        cp_async16(kdst, kp);
        cp_async16(kdst + 32 * KVSTR_B, kp + (size_t)32 * ldkv);
        cp_async16(vdst, vp);
        cp_async16(vdst + 32 * KVSTR_B, vp + (size_t)32 * ldkv);
    };

    float oacc[8][4];
    #pragma unroll
    for (int i = 0; i < 8; i++)
        #pragma unroll
        for (int e = 0; e < 4; e++) oacc[i][e] = 0.0f;
    float lacc[4] = {0.0f, 0.0f, 0.0f, 0.0f};
    float mstate0 = -1e30f, mstate1 = -1e30f;

    const int nt = Tkv >> 6;
    prefetch(0); cp_commit();

    for (int kt = 0; kt < nt; kt++) {
        if (kt + 1 < nt) { prefetch(kt + 1); cp_commit(); cp_wait<1>(); }
        else             { cp_wait<0>(); }
        __syncthreads();

        const uint32_t kbase = sbase + (kt & 1) * KTILE_B;
        const uint32_t vbase = kbase + 2 * KTILE_B;

        float sacc[8][4];
        #pragma unroll
        for (int nf = 0; nf < 8; nf++)
            #pragma unroll
            for (int e = 0; e < 4; e++) sacc[nf][e] = 0.0f;

        #pragma unroll
        for (int nf = 0; nf < 8; nf++) {
            uint32_t k0, k1, k2, k3, k4, k5, k6, k7;
            uint32_t base = kbase + nf * (8 * KVSTR_B) + loff_k;
            ldm_x4(k0, k1, k2, k3, base);
            ldm_x4(k4, k5, k6, k7, base + 64);
            uint32_t bf[2];
            bf[0] = k0; bf[1] = k1; mma_f16(sacc[nf], qf[0], bf);
            bf[0] = k2; bf[1] = k3; mma_f16(sacc[nf], qf[1], bf);
            bf[0] = k4; bf[1] = k5; mma_f16(sacc[nf], qf[2], bf);
            bf[0] = k6; bf[1] = k7; mma_f16(sacc[nf], qf[3], bf);
        }

        float mx0 = -1e30f, mx1 = -1e30f;
        #pragma unroll
        for (int nf = 0; nf < 8; nf++) {
            mx0 = fmaxf(mx0, fmaxf(sacc[nf][0], sacc[nf][1]));
            mx1 = fmaxf(mx1, fmaxf(sacc[nf][2], sacc[nf][3]));
        }
        mx0 = fmaxf(mx0, __shfl_xor_sync(0xffffffffu, mx0, 1));
        mx0 = fmaxf(mx0, __shfl_xor_sync(0xffffffffu, mx0, 2));
        mx1 = fmaxf(mx1, __shfl_xor_sync(0xffffffffu, mx1, 1));
        mx1 = fmaxf(mx1, __shfl_xor_sync(0xffffffffu, mx1, 2));
        float mn0 = fmaxf(mstate0, mx0), mn1 = fmaxf(mstate1, mx1);
        float corr0 = exp2f(mstate0 - mn0), corr1 = exp2f(mstate1 - mn1);
        mstate0 = mn0; mstate1 = mn1;

        uint32_t pf[8][2];
        #pragma unroll
        for (int nf = 0; nf < 8; nf++) {
            pf[nf][0] = ex2h2(packh2(sacc[nf][0] - mn0, sacc[nf][1] - mn0));
            pf[nf][1] = ex2h2(packh2(sacc[nf][2] - mn1, sacc[nf][3] - mn1));
        }

        #pragma unroll
        for (int nf = 0; nf < 8; nf++) {
            oacc[nf][0] *= corr0; oacc[nf][1] *= corr0;
            oacc[nf][2] *= corr1; oacc[nf][3] *= corr1;
        }
        lacc[0] *= corr0; lacc[1] *= corr0; lacc[2] *= corr1; lacc[3] *= corr1;

        const uint32_t onesf[2] = {ONESH2, ONESH2};
        #pragma unroll
        for (int kg = 0; kg < 4; kg++) {
            uint32_t af[4];
            af[0] = pf[2*kg][0];
            af[1] = pf[2*kg][1];
            af[2] = pf[2*kg+1][0];
            af[3] = pf[2*kg+1][1];
            mma_f16(lacc, af, onesf);
            #pragma unroll
            for (int nfp = 0; nfp < 4; nfp++) {
                uint32_t v0, v1, v2, v3;
                ldm_x4t(v0, v1, v2, v3, vbase + kg * (16 * KVSTR_B) + nfp * 32 + loff_v);
                uint32_t bf[2];
                bf[0] = v0; bf[1] = v1; mma_f16(oacc[2*nfp],     af, bf);
                bf[0] = v2; bf[1] = v3; mma_f16(oacc[2*nfp + 1], af, bf);
            }
        }
        __syncthreads();
    }

    float inv0 = 1.0f / lacc[0], inv1 = 1.0f / lacc[2];
    int row0 = brow + m0 + lr, row1 = row0 + 8;
    #pragma unroll
    for (int nf = 0; nf < 8; nf++) {
        int col = h * HS + nf * 8 + 2 * lc;
        float2 rA = *(const float2*)(xres + (size_t)row0 * D + col);
        float2 rB = *(const float2*)(xres + (size_t)row1 * D + col);
        *(float2*)(out + (size_t)row0 * D + col) =
            make_float2(rA.x + oacc[nf][0] * inv0, rA.y + oacc[nf][1] * inv0);
        *(float2*)(out + (size_t)row1 * D + col) =
            make_float2(rB.x + oacc[nf][2] * inv1, rB.y + oacc[nf][3] * inv1);
    }
}

// ---------------- host launch (3-stream pipelined graph) ----------------
extern "C" void kernel_launch(void* const* d_in, const int* in_sizes, int n_in,
                              void* d_out, int out_size) {
    const float* x0    = (const float*)d_in[0];
    const float* ctx   = (const float*)d_in[1];
    const float* ln1_w = (const float*)d_in[2];
    const float* ln1_b = (const float*)d_in[3];
    const float* sWq   = (const float*)d_in[4];
    const float* sbq   = (const float*)d_in[5];
    const float* sWk   = (const float*)d_in[6];
    const float* sbk   = (const float*)d_in[7];
    const float* sWv   = (const float*)d_in[8];
    const float* sbv   = (const float*)d_in[9];
    const float* ln2_w = (const float*)d_in[10];
    const float* ln2_b = (const float*)d_in[11];
    const float* cWq   = (const float*)d_in[12];
    const float* cbq   = (const float*)d_in[13];
    const float* cWk   = (const float*)d_in[14];
    const float* cbk   = (const float*)d_in[15];
    const float* cWv   = (const float*)d_in[16];
    const float* cbv   = (const float*)d_in[17];
    const float* ln3_w = (const float*)d_in[18];
    const float* ln3_b = (const float*)d_in[19];
    const float* W1    = (const float*)d_in[20];
    const float* b1    = (const float*)d_in[21];
    const float* W2    = (const float*)d_in[22];
    const float* b2    = (const float*)d_in[23];
    float* outp = (float*)d_out;

    __half *ln, *q, *qkv, *kvc, *ctr, *ffh, *wts, *wtc, *w1t, *w2t;
    float *x1, *x2, *bqkv, *bkvc;
    cudaGetSymbolAddress((void**)&ln,   g_ln);
    cudaGetSymbolAddress((void**)&q,    g_q);
    cudaGetSymbolAddress((void**)&qkv,  g_qkv);
    cudaGetSymbolAddress((void**)&kvc,  g_kvc);
    cudaGetSymbolAddress((void**)&x1,   g_x1);
    cudaGetSymbolAddress((void**)&x2,   g_x2);
    cudaGetSymbolAddress((void**)&ctr,  g_ctx);
    cudaGetSymbolAddress((void**)&ffh,  g_ffh);
    cudaGetSymbolAddress((void**)&wts,  g_wts);
    cudaGetSymbolAddress((void**)&wtc,  g_wtc);
    cudaGetSymbolAddress((void**)&w1t,  g_w1t);
    cudaGetSymbolAddress((void**)&w2t,  g_w2t);
    cudaGetSymbolAddress((void**)&bqkv, g_bqkv);
    cudaGetSymbolAddress((void**)&bkvc, g_bkvc);

    const int SMEM_GEMM = STAGES * TILEWW * 2 * 4;   // 81920 B
    const int SMEM_ATTN = 4 * KTILE_B;               // 36864 B

    static cudaStream_t s1 = nullptr, s2 = nullptr;
    static cudaEvent_t eFork, eW1, eW2, eKV, eW3, eL1, eA1B, eL3, eF2B;
    static bool inited = false;
    if (!inited) {
        cudaStreamCreateWithFlags(&s1, cudaStreamNonBlocking);
        cudaStreamCreateWithFlags(&s2, cudaStreamNonBlocking);
        cudaEventCreateWithFlags(&eFork, cudaEventDisableTiming);
        cudaEventCreateWithFlags(&eW1,   cudaEventDisableTiming);
        cudaEventCreateWithFlags(&eW2,   cudaEventDisableTiming);
        cudaEventCreateWithFlags(&eKV,   cudaEventDisableTiming);
        cudaEventCreateWithFlags(&eW3,   cudaEventDisableTiming);
        cudaEventCreateWithFlags(&eL1,   cudaEventDisableTiming);
        cudaEventCreateWithFlags(&eA1B,  cudaEventDisableTiming);
        cudaEventCreateWithFlags(&eL3,   cudaEventDisableTiming);
        cudaEventCreateWithFlags(&eF2B,  cudaEventDisableTiming);
        cudaFuncSetAttribute(gemm_mma<0, false, true >, cudaFuncAttributeMaxDynamicSharedMemorySize, SMEM_GEMM);
        cudaFuncSetAttribute(gemm_mma<1, false, true >, cudaFuncAttributeMaxDynamicSharedMemorySize, SMEM_GEMM);
        cudaFuncSetAttribute(gemm_mma<0, true,  false>, cudaFuncAttributeMaxDynamicSharedMemorySize, SMEM_GEMM);
        cudaFuncSetAttribute(attn_tc, cudaFuncAttributeMaxDynamicSharedMemorySize, SMEM_ATTN);
        inited = true;
    }

    dim3 gqkvH(3 * D / 128, MH / 128);   // (18, 32) half rows
    dim3 gq   (D / 128, MQ / 128);       // (6, 64)
    dim3 gkvc (2 * D / 128, MKV / 128);  // (12, 16)
    dim3 gff1H(FFD / 128, MH / 128);     // (24, 32)
    dim3 gff2H(D / 128, MH / 128);       // (6, 32)
    dim3 gatnH(TT / 128, HH, BB / 2);    // (8, 12, 4) half batches

    // ---- fork side stream s1 (weight prep) ----
    cudaEventRecord(eFork, 0);
    cudaStreamWaitEvent(s1, eFork, 0);
    cudaStreamWaitEvent(s2, eFork, 0);

    repack_kernel<<<dim3(HS / 32, D / 32, 3 * HH), dim3(32, 8), 0, s1>>>(sWq, sWk, sWv, wts);
    concat3_kernel<<<9, 256, 0, s1>>>(sbq, sbk, sbv, bqkv);
    cudaEventRecord(eW1, s1);
    round_kernel<<<(MKV * D + 255) / 256, 256, 0, s1>>>(ctx, ctr, MKV * D);
    repack_kernel<<<dim3(HS / 32, D / 32, 3 * HH), dim3(32, 8), 0, s1>>>(cWq, cWk, cWv, wtc);
    concat2_kernel<<<6, 256, 0, s1>>>(cbk, cbv, bkvc);
    cudaEventRecord(eW2, s1);
    gemm_mma<0, false, true><<<gkvc, 256, SMEM_GEMM, s1>>>(ctr, wtc + DD, bkvc, nullptr, kvc, MKV, 2 * D, D);
    cudaEventRecord(eKV, s1);
    transpose_kernel<<<dim3(FFD / 32, D / 32), dim3(32, 8), 0, s1>>>(W1, w1t, D, FFD);
    transpose_kernel<<<dim3(D / 32, FFD / 32), dim3(32, 8), 0, s1>>>(W2, w2t, FFD, D);
    cudaEventRecord(eW3, s1);

    // ---- block 1: LN, then qkv+attn split by batch halves (main = batches 0-3, s2 = 4-7) ----
    ln_kernel<<<MQ / 8, 256>>>(x0, ln1_w, ln1_b, ln);
    cudaEventRecord(eL1, 0);

    cudaStreamWaitEvent(0, eW1, 0);
    gemm_mma<0, false, true><<<gqkvH, 256, SMEM_GEMM>>>(ln, wts, bqkv, nullptr, qkv, MQ, 3 * D, D);
    attn_tc<<<gatnH, 256, SMEM_ATTN>>>(qkv, 3 * D, qkv + D, qkv + 2 * D, 3 * D, x0, x1, TT, TT);

    cudaStreamWaitEvent(s2, eL1, 0);
    cudaStreamWaitEvent(s2, eW1, 0);
    gemm_mma<0, false, true><<<gqkvH, 256, SMEM_GEMM, s2>>>(
        ln + (size_t)MH * D, wts, bqkv, nullptr, qkv + (size_t)MH * 3 * D, MQ, 3 * D, D);
    attn_tc<<<gatnH, 256, SMEM_ATTN, s2>>>(
        qkv + (size_t)MH * 3 * D, 3 * D,
        qkv + (size_t)MH * 3 * D + D, qkv + (size_t)MH * 3 * D + 2 * D, 3 * D,
        x0 + (size_t)MH * D, x1 + (size_t)MH * D, TT, TT);
    cudaEventRecord(eA1B, s2);

    // ---- block 2: cross attention (whole) ----
    cudaStreamWaitEvent(0, eA1B, 0);
    ln_kernel<<<MQ / 8, 256>>>(x1, ln2_w, ln2_b, ln);
    cudaStreamWaitEvent(0, eW2, 0);
    gemm_mma<0, false, true><<<gq, 256, SMEM_GEMM>>>(ln, wtc, cbq, nullptr, q, MQ, D, D);
    cudaStreamWaitEvent(0, eKV, 0);
    attn_tc<<<dim3(TT / 128, HH, BB), 256, SMEM_ATTN>>>(q, D, kvc, kvc + D, 2 * D,
                                                        x1, x2, TT, TCC);

    // ---- block 3: FFN split by row halves (main = rows 0-4095, s2 = 4096-8191) ----
    ln_kernel<<<MQ / 8, 256>>>(x2, ln3_w, ln3_b, ln);
    cudaEventRecord(eL3, 0);

    cudaStreamWaitEvent(0, eW3, 0);
    gemm_mma<1, false, true ><<<gff1H, 256, SMEM_GEMM>>>(ln,  w1t, b1, nullptr, ffh,  MQ, FFD, D);
    gemm_mma<0, true,  false><<<gff2H, 256, SMEM_GEMM>>>(ffh, w2t, b2, x2,      outp, MQ, D, FFD);

    cudaStreamWaitEvent(s2, eL3, 0);
    cudaStreamWaitEvent(s2, eW3, 0);
    gemm_mma<1, false, true ><<<gff1H, 256, SMEM_GEMM, s2>>>(
        ln + (size_t)MH * D, w1t, b1, nullptr, ffh + (size_t)MH * FFD, MQ, FFD, D);
    gemm_mma<0, true,  false><<<gff2H, 256, SMEM_GEMM, s2>>>(
        ffh + (size_t)MH * FFD, w2t, b2, x2 + (size_t)MH * D, outp + (size_t)MH * D, MQ, D, FFD);
    cudaEventRecord(eF2B, s2);

    cudaStreamWaitEvent(0, eF2B, 0);
}

// round 14
// speedup vs baseline: 1.2041x; 1.0247x over previous
#include <cuda_runtime.h>
#include <cuda_fp16.h>
#include <math.h>
#include <stdint.h>

#define D   768
#define HH  12
#define HS  64
#define BB  8
#define TT  1024
#define TCC 256
#define FFD 3072
#define MQ  (BB*TT)    // 8192 rows
#define MKV (BB*TCC)   // 2048 rows
#define DD  (D*D)
#define MH  (MQ/2)     // 4096 row half (= 4 batches)

// ---------------- scratch (device globals; no allocs allowed) ----------------
__device__ __half g_ln [MQ*D];
__device__ __half g_q  [MQ*D];                 // cross-attn Q
__device__ __half g_qkv[(size_t)MQ*3*D];       // self-attn fused QKV [8192 x 2304]
__device__ __half g_kvc[(size_t)MKV*2*D];      // cross-attn fused KV [2048 x 1536]
__device__ float  g_x1 [MQ*D];
__device__ float  g_x2 [MQ*D];
__device__ __half g_ctx[MKV*D];                // fp16 context
__device__ __half g_ffh[(size_t)MQ*FFD];
__device__ __half g_wts[3*DD];                 // repacked self QKV weights
__device__ __half g_wtc[3*DD];                 // repacked cross QKV weights
__device__ __half g_w1t[(size_t)FFD*D];        // W1^T : [FF, D]
__device__ __half g_w2t[(size_t)D*FFD];        // W2^T : [D, FF]
__device__ float  g_bqkv[3*D];
__device__ float  g_bkvc[2*D];

// ---------------- helpers ----------------
__device__ __forceinline__ uint32_t smem_u32(const void* p) {
    uint32_t a;
    asm("{ .reg .u64 t; cvta.to.shared.u64 t, %1; cvt.u32.u64 %0, t; }" : "=r"(a) : "l"(p));
    return a;
}
__device__ __forceinline__ void cp_async16(uint32_t dst, const void* src) {
    asm volatile("cp.async.cg.shared.global [%0], [%1], 16;" :: "r"(dst), "l"(src));
}
__device__ __forceinline__ void cp_commit() { asm volatile("cp.async.commit_group;"); }
template<int N> __device__ __forceinline__ void cp_wait() {
    asm volatile("cp.async.wait_group %0;" :: "n"(N));
}
__device__ __forceinline__ void mma_f16(float* c, const uint32_t* a, const uint32_t* b) {
    asm volatile("mma.sync.aligned.m16n8k16.row.col.f32.f16.f16.f32 "
        "{%0,%1,%2,%3}, {%4,%5,%6,%7}, {%8,%9}, {%0,%1,%2,%3};"
        : "+f"(c[0]), "+f"(c[1]), "+f"(c[2]), "+f"(c[3])
        : "r"(a[0]), "r"(a[1]), "r"(a[2]), "r"(a[3]), "r"(b[0]), "r"(b[1]));
}
__device__ __forceinline__ void ldm_x4(uint32_t& r0, uint32_t& r1, uint32_t& r2, uint32_t& r3, uint32_t a) {
    asm volatile("ldmatrix.sync.aligned.m8n8.x4.shared.b16 {%0,%1,%2,%3}, [%4];"
        : "=r"(r0), "=r"(r1), "=r"(r2), "=r"(r3) : "r"(a));
}
__device__ __forceinline__ void ldm_x4t(uint32_t& r0, uint32_t& r1, uint32_t& r2, uint32_t& r3, uint32_t a) {
    asm volatile("ldmatrix.sync.aligned.m8n8.x4.trans.shared.b16 {%0,%1,%2,%3}, [%4];"
        : "=r"(r0), "=r"(r1), "=r"(r2), "=r"(r3) : "r"(a));
}
__device__ __forceinline__ uint32_t packh2(float x, float y) {
    __half2 h = __floats2half2_rn(x, y);
    return *(uint32_t*)&h;
}
__device__ __forceinline__ uint32_t ex2h2(uint32_t x) {
    uint32_t r; asm("ex2.approx.f16x2 %0, %1;" : "=r"(r) : "r"(x));
    return r;
}
// fast SiLU via MUFU ex2 + rcp
__device__ __forceinline__ float silu_f(float z) {
    float e, r;
    float t = -1.4426950408889634f * z;
    asm("ex2.approx.f32 %0, %1;" : "=f"(e) : "f"(t));
    float d = 1.0f + e;
    asm("rcp.approx.f32 %0, %1;" : "=f"(r) : "f"(d));
    return z * r;
}

// ---------------- LayerNorm: warp-per-row, no smem, fp16 out ----------------
__global__ void ln_kernel(const float* __restrict__ x, const float* __restrict__ w,
                          const float* __restrict__ b, __half* __restrict__ out) {
    int lane = threadIdx.x & 31, wrp = threadIdx.x >> 5;
    int row = blockIdx.x * 8 + wrp;
    const float* xr = x + (size_t)row * D;

    float4 v[6];
    float s = 0.0f, sq = 0.0f;
    #pragma unroll
    for (int j = 0; j < 6; j++) {
        v[j] = *(const float4*)(xr + lane * 4 + j * 128);
        s  += (v[j].x + v[j].y) + (v[j].z + v[j].w);
        sq += v[j].x*v[j].x + v[j].y*v[j].y + v[j].z*v[j].z + v[j].w*v[j].w;
    }
    #pragma unroll
    for (int o = 16; o; o >>= 1) {
        s  += __shfl_xor_sync(0xffffffffu, s,  o);
        sq += __shfl_xor_sync(0xffffffffu, sq, o);
    }
    float mu  = s * (1.0f / D);
    float inv = rsqrtf(sq * (1.0f / D) - mu * mu + 1e-5f);

    __half* orow = out + (size_t)row * D;
    #pragma unroll
    for (int j = 0; j < 6; j++) {
        int c = lane * 4 + j * 128;
        float4 wv = *(const float4*)(w + c);
        float4 bv = *(const float4*)(b + c);
        __half2 h0 = __floats2half2_rn((v[j].x - mu) * inv * wv.x + bv.x,
                                       (v[j].y - mu) * inv * wv.y + bv.y);
        __half2 h1 = __floats2half2_rn((v[j].z - mu) * inv * wv.z + bv.z,
                                       (v[j].w - mu) * inv * wv.w + bv.w);
        uint2 pk = make_uint2(*(uint32_t*)&h0, *(uint32_t*)&h1);
        *(uint2*)(orow + c) = pk;
    }
}

// ------------- repack [H,D,HS] QKV weights -> [N rows, K] k-major fp16 (coalesced) -------------
__global__ void repack_kernel(const float* __restrict__ Wq, const float* __restrict__ Wk,
                              const float* __restrict__ Wv, __half* __restrict__ dst) {
    __shared__ float tile[32][33];
    int m = blockIdx.z / HH, h = blockIdx.z % HH;
    const float* W = (m == 0) ? Wq : ((m == 1) ? Wk : Wv);
    const float* Wh = W + (size_t)h * D * HS;
    int e0 = blockIdx.x * 32, d0 = blockIdx.y * 32;
    #pragma unroll
    for (int i = 0; i < 32; i += 8)
        tile[threadIdx.y + i][threadIdx.x] = Wh[(size_t)(d0 + threadIdx.y + i) * HS + e0 + threadIdx.x];
    __syncthreads();
    __half* dm = dst + (size_t)m * DD;
    #pragma unroll
    for (int i = 0; i < 32; i += 8)
        dm[(size_t)(h * HS + e0 + threadIdx.y + i) * D + d0 + threadIdx.x] =
            __float2half_rn(tile[threadIdx.x][threadIdx.y + i]);
}

// ------------- tiled transpose + fp16 convert -------------
__global__ void transpose_kernel(const float* __restrict__ src, __half* __restrict__ dst,
                                 int R, int C) {
    __shared__ float tile[32][33];
    int bx = blockIdx.x * 32, by = blockIdx.y * 32;
    int x = bx + threadIdx.x;
    #pragma unroll
    for (int i = 0; i < 32; i += 8)
        tile[threadIdx.y + i][threadIdx.x] = src[(size_t)(by + threadIdx.y + i) * C + x];
    __syncthreads();
    int x2 = by + threadIdx.x;
    #pragma unroll
    for (int i = 0; i < 32; i += 8)
        dst[(size_t)(bx + threadIdx.y + i) * R + x2] = __float2half_rn(tile[threadIdx.x][threadIdx.y + i]);
}

__global__ void round_kernel(const float* __restrict__ src, __half* __restrict__ dst, int n) {
    int i = blockIdx.x * blockDim.x + threadIdx.x;
    if (i < n) dst[i] = __float2half_rn(src[i]);
}
__global__ void concat3_kernel(const float* __restrict__ a, const float* __restrict__ b,
                               const float* __restrict__ c, float* __restrict__ dst) {
    int i = blockIdx.x * blockDim.x + threadIdx.x;
    if (i < D) dst[i] = a[i];
    else if (i < 2 * D) dst[i] = b[i - D];
    else if (i < 3 * D) dst[i] = c[i - 2 * D];
}
__global__ void concat2_kernel(const float* __restrict__ a, const float* __restrict__ b,
                               float* __restrict__ dst) {
    int i = blockIdx.x * blockDim.x + threadIdx.x;
    if (i < D) dst[i] = a[i];
    else if (i < 2 * D) dst[i] = b[i - D];
}

// =======================================================================================
// fp16 mma.sync GEMM: BM=BN=128, BK=32, 256 threads, 4-stage cp.async, ldmatrix frags.
// =======================================================================================
#define WS     20
#define STAGES 4
#define TILEWW (128 * WS)

template<int ACT, bool RES, bool OUTH>
__global__ __launch_bounds__(256)
void gemm_mma(const __half* __restrict__ A, const __half* __restrict__ Bt,
              const float* __restrict__ bias, const float* __restrict__ res,
              void* __restrict__ Cv, int M, int N, int K) {
    extern __shared__ uint32_t smw[];

    const int tid  = threadIdx.x;
    const int lane = tid & 31, wid = tid >> 5;
    const int warp_m = wid & 1, warp_n = wid >> 1;
    const int bm = blockIdx.y * 128, bn = blockIdx.x * 128;
    const uint32_t sbase = smem_u32(smw);

    const int r0l = tid >> 2, subl = tid & 3;
    const __half* Ag = A + (size_t)(bm + r0l) * K + subl * 8;
    const __half* Bg = Bt + (size_t)(bn + r0l) * K + subl * 8;
    const uint32_t adst0 = sbase + (uint32_t)(r0l * WS + subl * 4) * 4u;
    const uint32_t bdst0 = sbase + (uint32_t)(STAGES * TILEWW + r0l * WS + subl * 4) * 4u;

    const int nt = K >> 5;

    auto prefetch = [&](int kt) {
        int s = kt % STAGES;
        uint32_t ad = adst0 + (uint32_t)(s * TILEWW) * 4u;
        uint32_t bd = bdst0 + (uint32_t)(s * TILEWW) * 4u;
        const __half* ag = Ag + kt * 32;
        const __half* bg = Bg + kt * 32;
        cp_async16(ad, ag);
        cp_async16(ad + (uint32_t)(64 * WS) * 4u, ag + (size_t)64 * K);
        cp_async16(bd, bg);
        cp_async16(bd + (uint32_t)(64 * WS) * 4u, bg + (size_t)64 * K);
    };

    float acc[4][4][4];
    #pragma unroll
    for (int mi = 0; mi < 4; mi++)
        #pragma unroll
        for (int ni = 0; ni < 4; ni++)
            #pragma unroll
            for (int e = 0; e < 4; e++) acc[mi][ni][e] = 0.0f;

    #pragma unroll
    for (int s = 0; s < STAGES - 1; s++) { prefetch(s); cp_commit(); }

    const uint32_t a_l = (uint32_t)((warp_m * 64 + (lane & 15)) * WS) * 4u + (uint32_t)((lane >> 4) * 16);
    const uint32_t b_l = (uint32_t)(STAGES * TILEWW) * 4u +
                         (uint32_t)((warp_n * 32 + (lane & 7) + ((lane >> 4) << 3)) * WS) * 4u +
                         (uint32_t)(((lane >> 3) & 1) * 16);

    for (int kt = 0; kt < nt; kt++) {
        cp_wait<STAGES - 2>();
        __syncthreads();
        if (kt + STAGES - 1 < nt) prefetch(kt + STAGES - 1);
        cp_commit();

        int s = kt % STAGES;
        const uint32_t soff = (uint32_t)(s * TILEWW) * 4u;
        const uint32_t abase_s = sbase + soff + a_l;
        const uint32_t bbase_s = sbase + soff + b_l;

        #pragma unroll
        for (int ks = 0; ks < 2; ks++) {
            const uint32_t koff = (uint32_t)(ks * 32);
            uint32_t af[4][4], bf[4][2];
            #pragma unroll
            for (int mi = 0; mi < 4; mi++)
                ldm_x4(af[mi][0], af[mi][1], af[mi][2], af[mi][3],
                       abase_s + (uint32_t)(mi * 16 * WS) * 4u + koff);
            ldm_x4(bf[0][0], bf[0][1], bf[1][0], bf[1][1], bbase_s + koff);
            ldm_x4(bf[2][0], bf[2][1], bf[3][0], bf[3][1],
                   bbase_s + (uint32_t)(16 * WS) * 4u + koff);
            #pragma unroll
            for (int mi = 0; mi < 4; mi++)
                #pragma unroll
                for (int ni = 0; ni < 4; ni++)
                    mma_f16(acc[mi][ni], af[mi], bf[ni]);
        }
    }

    const int lr = lane >> 2, lc = lane & 3;
    #pragma unroll
    for (int mi = 0; mi < 4; mi++) {
        int r0 = bm + warp_m * 64 + mi * 16 + lr;
        #pragma unroll
        for (int ni = 0; ni < 4; ni++) {
            int c0 = bn + warp_n * 32 + ni * 8 + 2 * lc;
            float b0 = bias[c0], b1 = bias[c0 + 1];
            float v00 = acc[mi][ni][0] + b0, v01 = acc[mi][ni][1] + b1;
            float v10 = acc[mi][ni][2] + b0, v11 = acc[mi][ni][3] + b1;
            if (ACT == 1) { v00 = silu_f(v00); v01 = silu_f(v01); v10 = silu_f(v10); v11 = silu_f(v11); }
            if (RES) {
                const float2 rA = *(const float2*)(res + (size_t)r0 * N + c0);
                const float2 rB = *(const float2*)(res + (size_t)(r0 + 8) * N + c0);
                v00 += rA.x; v01 += rA.y; v10 += rB.x; v11 += rB.y;
            }
            if (OUTH) {
                __half* Ch = (__half*)Cv;
                uint32_t p0 = packh2(v00, v01), p1 = packh2(v10, v11);
                *(uint32_t*)(Ch + (size_t)r0 * N + c0)       = p0;
                *(uint32_t*)(Ch + (size_t)(r0 + 8) * N + c0) = p1;
            } else {
                float* Cf = (float*)Cv;
                *(float2*)(Cf + (size_t)r0 * N + c0)       = make_float2(v00, v01);
                *(float2*)(Cf + (size_t)(r0 + 8) * N + c0) = make_float2(v10, v11);
            }
        }
    }
}

// =======================================================================================
// fp16 tensor-core flash attention: f16x2 exp2 + ones-MMA row sums.
// =======================================================================================
#define KVSTR_B 144
#define KTILE_B (64 * KVSTR_B)
#define ONESH2  0x3C003C00u

__global__ __launch_bounds__(256)
void attn_tc(const __half* __restrict__ Q, int ldq,
             const __half* __restrict__ Kg, const __half* __restrict__ Vg, int ldkv,
             const float* __restrict__ xres, float* __restrict__ out,
             int Tq, int Tkv) {
    extern __shared__ uint32_t smw[];
    const uint32_t sbase = smem_u32(smw);

    const int tid = threadIdx.x;
    const int lane = tid & 31, wid = tid >> 5;
    const int lr = lane >> 2, lc = lane & 3;
    const int h = blockIdx.y, b = blockIdx.z;
    const int brow = b * Tq + blockIdx.x * 128;
    const int m0 = wid * 16;

    const __half* Kb = Kg + (size_t)b * Tkv * ldkv + h * HS;
    const __half* Vb = Vg + (size_t)b * Tkv * ldkv + h * HS;

    const float SC2 = 0.125f * 1.4426950408889634f;
    uint32_t qf[4][4];
    {
        const __half* Qp = Q + (size_t)(brow + m0) * ldq + h * HS;
        #pragma unroll
        for (int ks = 0; ks < 4; ks++) {
            int c = ks * 16 + 2 * lc;
            #pragma unroll
            for (int e = 0; e < 4; e++) {
                int rr = (e & 1) ? lr + 8 : lr;
                int cc = c + ((e >> 1) ? 8 : 0);
                __half2 hv = *(const __half2*)(Qp + (size_t)rr * ldq + cc);
                float2 f = __half22float2(hv);
                qf[ks][e] = packh2(f.x * SC2, f.y * SC2);
            }
        }
    }

    const int rl = lane & 7;
    const uint32_t loff_k = (uint32_t)(rl * KVSTR_B + ((lane >> 3) * 16));
    const uint32_t loff_v = (uint32_t)(((((lane >> 3) & 1) * 8 + rl) * KVSTR_B) + ((lane >> 4) * 16));

    const int lrow = tid >> 3, lsub = tid & 7;
    auto prefetch = [&](int kt) {
        int buf = kt & 1;
        uint32_t kdst = sbase + buf * KTILE_B + lrow * KVSTR_B + lsub * 16;
        uint32_t vdst = kdst + 2 * KTILE_B;
        const __half* kp = Kb + (size_t)(kt * 64 + lrow) * ldkv + lsub * 8;
        const __half* vp = Vb + (size_t)(kt * 64 + lrow) * ldkv + lsub * 8;
        cp_async16(kdst, kp);
        cp_async16(kdst + 32 * KVSTR_B, kp + (size_t)32 * ldkv);
        cp_async16(vdst, vp);
        cp_async16(vdst + 32 * KVSTR_B, vp + (size_t)32 * ldkv);
    };

    float oacc[8][4];
    #pragma unroll
    for (int i = 0; i < 8; i++)
        #pragma unroll
        for (int e = 0; e < 4; e++) oacc[i][e] = 0.0f;
    float lacc[4] = {0.0f, 0.0f, 0.0f, 0.0f};
    float mstate0 = -1e30f, mstate1 = -1e30f;

    const int nt = Tkv >> 6;
    prefetch(0); cp_commit();

    for (int kt = 0; kt < nt; kt++) {
        if (kt + 1 < nt) { prefetch(kt + 1); cp_commit(); cp_wait<1>(); }
        else             { cp_wait<0>(); }
        __syncthreads();

        const uint32_t kbase = sbase + (kt & 1) * KTILE_B;
        const uint32_t vbase = kbase + 2 * KTILE_B;

        float sacc[8][4];
        #pragma unroll
        for (int nf = 0; nf < 8; nf++)
            #pragma unroll
            for (int e = 0; e < 4; e++) sacc[nf][e] = 0.0f;

        #pragma unroll
        for (int nf = 0; nf < 8; nf++) {
            uint32_t k0, k1, k2, k3, k4, k5, k6, k7;
            uint32_t base = kbase + nf * (8 * KVSTR_B) + loff_k;
            ldm_x4(k0, k1, k2, k3, base);
            ldm_x4(k4, k5, k6, k7, base + 64);
            uint32_t bf[2];
            bf[0] = k0; bf[1] = k1; mma_f16(sacc[nf], qf[0], bf);
            bf[0] = k2; bf[1] = k3; mma_f16(sacc[nf], qf[1], bf);
            bf[0] = k4; bf[1] = k5; mma_f16(sacc[nf], qf[2], bf);
            bf[0] = k6; bf[1] = k7; mma_f16(sacc[nf], qf[3], bf);
        }

        float mx0 = -1e30f, mx1 = -1e30f;
        #pragma unroll
        for (int nf = 0; nf < 8; nf++) {
            mx0 = fmaxf(mx0, fmaxf(sacc[nf][0], sacc[nf][1]));
            mx1 = fmaxf(mx1, fmaxf(sacc[nf][2], sacc[nf][3]));
        }
        mx0 = fmaxf(mx0, __shfl_xor_sync(0xffffffffu, mx0, 1));
        mx0 = fmaxf(mx0, __shfl_xor_sync(0xffffffffu, mx0, 2));
        mx1 = fmaxf(mx1, __shfl_xor_sync(0xffffffffu, mx1, 1));
        mx1 = fmaxf(mx1, __shfl_xor_sync(0xffffffffu, mx1, 2));
        float mn0 = fmaxf(mstate0, mx0), mn1 = fmaxf(mstate1, mx1);
        float corr0 = exp2f(mstate0 - mn0), corr1 = exp2f(mstate1 - mn1);
        mstate0 = mn0; mstate1 = mn1;

        uint32_t pf[8][2];
        #pragma unroll
        for (int nf = 0; nf < 8; nf++) {
            pf[nf][0] = ex2h2(packh2(sacc[nf][0] - mn0, sacc[nf][1] - mn0));
            pf[nf][1] = ex2h2(packh2(sacc[nf][2] - mn1, sacc[nf][3] - mn1));
        }

        #pragma unroll
        for (int nf = 0; nf < 8; nf++) {
            oacc[nf][0] *= corr0; oacc[nf][1] *= corr0;
            oacc[nf][2] *= corr1; oacc[nf][3] *= corr1;
        }
        lacc[0] *= corr0; lacc[1] *= corr0; lacc[2] *= corr1; lacc[3] *= corr1;

        const uint32_t onesf[2] = {ONESH2, ONESH2};
        #pragma unroll
        for (int kg = 0; kg < 4; kg++) {
            uint32_t af[4];
            af[0] = pf[2*kg][0];
            af[1] = pf[2*kg][1];
            af[2] = pf[2*kg+1][0];
            af[3] = pf[2*kg+1][1];
            mma_f16(lacc, af, onesf);
            #pragma unroll
            for (int nfp = 0; nfp < 4; nfp++) {
                uint32_t v0, v1, v2, v3;
                ldm_x4t(v0, v1, v2, v3, vbase + kg * (16 * KVSTR_B) + nfp * 32 + loff_v);
                uint32_t bf[2];
                bf[0] = v0; bf[1] = v1; mma_f16(oacc[2*nfp],     af, bf);
                bf[0] = v2; bf[1] = v3; mma_f16(oacc[2*nfp + 1], af, bf);
            }
        }
        __syncthreads();
    }

    float inv0 = 1.0f / lacc[0], inv1 = 1.0f / lacc[2];
    int row0 = brow + m0 + lr, row1 = row0 + 8;
    #pragma unroll
    for (int nf = 0; nf < 8; nf++) {
        int col = h * HS + nf * 8 + 2 * lc;
        float2 rA = *(const float2*)(xres + (size_t)row0 * D + col);
        float2 rB = *(const float2*)(xres + (size_t)row1 * D + col);
        *(float2*)(out + (size_t)row0 * D + col) =
            make_float2(rA.x + oacc[nf][0] * inv0, rA.y + oacc[nf][1] * inv0);
        *(float2*)(out + (size_t)row1 * D + col) =
            make_float2(rB.x + oacc[nf][2] * inv1, rB.y + oacc[nf][3] * inv1);
    }
}

// ---------------- host launch: two independent half-pipelines + weight side stream ----------------
extern "C" void kernel_launch(void* const* d_in, const int* in_sizes, int n_in,
                              void* d_out, int out_size) {
    const float* x0    = (const float*)d_in[0];
    const float* ctx   = (const float*)d_in[1];
    const float* ln1_w = (const float*)d_in[2];
    const float* ln1_b = (const float*)d_in[3];
    const float* sWq   = (const float*)d_in[4];
    const float* sbq   = (const float*)d_in[5];
    const float* sWk   = (const float*)d_in[6];
    const float* sbk   = (const float*)d_in[7];
    const float* sWv   = (const float*)d_in[8];
    const float* sbv   = (const float*)d_in[9];
    const float* ln2_w = (const float*)d_in[10];
    const float* ln2_b = (const float*)d_in[11];
    const float* cWq   = (const float*)d_in[12];
    const float* cbq   = (const float*)d_in[13];
    const float* cWk   = (const float*)d_in[14];
    const float* cbk   = (const float*)d_in[15];
    const float* cWv   = (const float*)d_in[16];
    const float* cbv   = (const float*)d_in[17];
    const float* ln3_w = (const float*)d_in[18];
    const float* ln3_b = (const float*)d_in[19];
    const float* W1    = (const float*)d_in[20];
    const float* b1    = (const float*)d_in[21];
    const float* W2    = (const float*)d_in[22];
    const float* b2    = (const float*)d_in[23];
    float* outp = (float*)d_out;

    __half *ln, *q, *qkv, *kvc, *ctr, *ffh, *wts, *wtc, *w1t, *w2t;
    float *x1, *x2, *bqkv, *bkvc;
    cudaGetSymbolAddress((void**)&ln,   g_ln);
    cudaGetSymbolAddress((void**)&q,    g_q);
    cudaGetSymbolAddress((void**)&qkv,  g_qkv);
    cudaGetSymbolAddress((void**)&kvc,  g_kvc);
    cudaGetSymbolAddress((void**)&x1,   g_x1);
    cudaGetSymbolAddress((void**)&x2,   g_x2);
    cudaGetSymbolAddress((void**)&ctr,  g_ctx);
    cudaGetSymbolAddress((void**)&ffh,  g_ffh);
    cudaGetSymbolAddress((void**)&wts,  g_wts);
    cudaGetSymbolAddress((void**)&wtc,  g_wtc);
    cudaGetSymbolAddress((void**)&w1t,  g_w1t);
    cudaGetSymbolAddress((void**)&w2t,  g_w2t);
    cudaGetSymbolAddress((void**)&bqkv, g_bqkv);
    cudaGetSymbolAddress((void**)&bkvc, g_bkvc);

    const int SMEM_GEMM = STAGES * TILEWW * 2 * 4;   // 81920 B
    const int SMEM_ATTN = 4 * KTILE_B;               // 36864 B

    static cudaStream_t s1 = nullptr, s2 = nullptr;
    static cudaEvent_t eFork, eW1, eW2, eKV, eW3, eDone;
    static bool inited = false;
    if (!inited) {
        cudaStreamCreateWithFlags(&s1, cudaStreamNonBlocking);
        cudaStreamCreateWithFlags(&s2, cudaStreamNonBlocking);
        cudaEventCreateWithFlags(&eFork, cudaEventDisableTiming);
        cudaEventCreateWithFlags(&eW1,   cudaEventDisableTiming);
        cudaEventCreateWithFlags(&eW2,   cudaEventDisableTiming);
        cudaEventCreateWithFlags(&eKV,   cudaEventDisableTiming);
        cudaEventCreateWithFlags(&eW3,   cudaEventDisableTiming);
        cudaEventCreateWithFlags(&eDone, cudaEventDisableTiming);
        cudaFuncSetAttribute(gemm_mma<0, false, true >, cudaFuncAttributeMaxDynamicSharedMemorySize, SMEM_GEMM);
        cudaFuncSetAttribute(gemm_mma<1, false, true >, cudaFuncAttributeMaxDynamicSharedMemorySize, SMEM_GEMM);
        cudaFuncSetAttribute(gemm_mma<0, true,  false>, cudaFuncAttributeMaxDynamicSharedMemorySize, SMEM_GEMM);
        cudaFuncSetAttribute(attn_tc, cudaFuncAttributeMaxDynamicSharedMemorySize, SMEM_ATTN);
        inited = true;
    }

    dim3 gqkvH(3 * D / 128, MH / 128);   // (18, 32)
    dim3 gqH  (D / 128, MH / 128);       // (6, 32)
    dim3 gkvc (2 * D / 128, MKV / 128);  // (12, 16)
    dim3 gff1H(FFD / 128, MH / 128);     // (24, 32)
    dim3 gff2H(D / 128, MH / 128);       // (6, 32)
    dim3 gatnH(TT / 128, HH, BB / 2);    // (8, 12, 4)

    // ---- fork: weight prep on s1 ----
    cudaEventRecord(eFork, 0);
    cudaStreamWaitEvent(s1, eFork, 0);
    cudaStreamWaitEvent(s2, eFork, 0);

    repack_kernel<<<dim3(HS / 32, D / 32, 3 * HH), dim3(32, 8), 0, s1>>>(sWq, sWk, sWv, wts);
    concat3_kernel<<<9, 256, 0, s1>>>(sbq, sbk, sbv, bqkv);
    cudaEventRecord(eW1, s1);
    round_kernel<<<(MKV * D + 255) / 256, 256, 0, s1>>>(ctx, ctr, MKV * D);
    repack_kernel<<<dim3(HS / 32, D / 32, 3 * HH), dim3(32, 8), 0, s1>>>(cWq, cWk, cWv, wtc);
    concat2_kernel<<<6, 256, 0, s1>>>(cbk, cbv, bkvc);
    cudaEventRecord(eW2, s1);
    gemm_mma<0, false, true><<<gkvc, 256, SMEM_GEMM, s1>>>(ctr, wtc + DD, bkvc, nullptr, kvc, MKV, 2 * D, D);
    cudaEventRecord(eKV, s1);
    transpose_kernel<<<dim3(FFD / 32, D / 32), dim3(32, 8), 0, s1>>>(W1, w1t, D, FFD);
    transpose_kernel<<<dim3(D / 32, FFD / 32), dim3(32, 8), 0, s1>>>(W2, w2t, FFD, D);
    cudaEventRecord(eW3, s1);

    // ---- half-pipeline launcher (stream st, row offset ro rows, batch offset bo) ----
    auto run_half = [&](cudaStream_t st, size_t ro, int bo) {
        const size_t oD  = ro * D;
        const size_t o3D = ro * 3 * D;
        const size_t oFF = ro * FFD;
        // block 1: self attention
        ln_kernel<<<MH / 8, 256, 0, st>>>(x0 + oD, ln1_w, ln1_b, ln + oD);
        cudaStreamWaitEvent(st, eW1, 0);
        gemm_mma<0, false, true><<<gqkvH, 256, SMEM_GEMM, st>>>(
            ln + oD, wts, bqkv, nullptr, qkv + o3D, MQ, 3 * D, D);
        attn_tc<<<gatnH, 256, SMEM_ATTN, st>>>(
            qkv + o3D, 3 * D, qkv + o3D + D, qkv + o3D + 2 * D, 3 * D,
            x0 + oD, x1 + oD, TT, TT);
        // block 2: cross attention
        ln_kernel<<<MH / 8, 256, 0, st>>>(x1 + oD, ln2_w, ln2_b, ln + oD);
        cudaStreamWaitEvent(st, eW2, 0);
        gemm_mma<0, false, true><<<gqH, 256, SMEM_GEMM, st>>>(
            ln + oD, wtc, cbq, nullptr, q + oD, MQ, D, D);
        cudaStreamWaitEvent(st, eKV, 0);
        attn_tc<<<gatnH, 256, SMEM_ATTN, st>>>(
            q + oD, D, kvc + (size_t)bo * TCC * 2 * D, kvc + (size_t)bo * TCC * 2 * D + D, 2 * D,
            x1 + oD, x2 + oD, TT, TCC);
        // block 3: FFN
        ln_kernel<<<MH / 8, 256, 0, st>>>(x2 + oD, ln3_w, ln3_b, ln + oD);
        cudaStreamWaitEvent(st, eW3, 0);
        gemm_mma<1, false, true ><<<gff1H, 256, SMEM_GEMM, st>>>(
            ln + oD, w1t, b1, nullptr, ffh + oFF, MQ, FFD, D);
        gemm_mma<0, true,  false><<<gff2H, 256, SMEM_GEMM, st>>>(
            ffh + oFF, w2t, b2, x2 + oD, outp + oD, MQ, D, FFD);
    };

    run_half(0,  0,        0);       // half A: batches 0-3, main stream
    run_half(s2, (size_t)MH, BB / 2); // half B: batches 4-7, stream s2
    cudaEventRecord(eDone, s2);
    cudaStreamWaitEvent(0, eDone, 0);
}

// round 16
// speedup vs baseline: 1.2099x; 1.0049x over previous
#include <cuda_runtime.h>
#include <cuda_fp16.h>
#include <math.h>
#include <stdint.h>

#define D   768
#define HH  12
#define HS  64
#define BB  8
#define TT  1024
#define TCC 256
#define FFD 3072
#define MQ  (BB*TT)    // 8192 rows
#define MKV (BB*TCC)   // 2048 rows
#define DD  (D*D)
#define MH  (MQ/2)     // 4096 row half (= 4 batches)

// ---------------- scratch (device globals; no allocs allowed) ----------------
__device__ __half g_ln [MQ*D];
__device__ __half g_q  [MQ*D];                 // cross-attn Q
__device__ __half g_qkv[(size_t)MQ*3*D];       // self-attn fused QKV [8192 x 2304]
__device__ __half g_kvc[(size_t)MKV*2*D];      // cross-attn fused KV [2048 x 1536]
__device__ float  g_x1 [MQ*D];
__device__ float  g_x2 [MQ*D];
__device__ __half g_ctx[MKV*D];                // fp16 context
__device__ __half g_ffh[(size_t)MQ*FFD];
__device__ __half g_wts[3*DD];                 // repacked self QKV weights
__device__ __half g_wtc[3*DD];                 // repacked cross QKV weights
__device__ __half g_w1t[(size_t)FFD*D];        // W1^T : [FF, D]
__device__ __half g_w2t[(size_t)D*FFD];        // W2^T : [D, FF]
__device__ float  g_bqkv[3*D];
__device__ float  g_bkvc[2*D];

// ---------------- helpers ----------------
__device__ __forceinline__ uint32_t smem_u32(const void* p) {
    uint32_t a;
    asm("{ .reg .u64 t; cvta.to.shared.u64 t, %1; cvt.u32.u64 %0, t; }" : "=r"(a) : "l"(p));
    return a;
}
__device__ __forceinline__ void cp_async16(uint32_t dst, const void* src) {
    asm volatile("cp.async.cg.shared.global [%0], [%1], 16;" :: "r"(dst), "l"(src));
}
__device__ __forceinline__ void cp_commit() { asm volatile("cp.async.commit_group;"); }
template<int N> __device__ __forceinline__ void cp_wait() {
    asm volatile("cp.async.wait_group %0;" :: "n"(N));
}
__device__ __forceinline__ void mma_f16(float* c, const uint32_t* a, const uint32_t* b) {
    asm volatile("mma.sync.aligned.m16n8k16.row.col.f32.f16.f16.f32 "
        "{%0,%1,%2,%3}, {%4,%5,%6,%7}, {%8,%9}, {%0,%1,%2,%3};"
        : "+f"(c[0]), "+f"(c[1]), "+f"(c[2]), "+f"(c[3])
        : "r"(a[0]), "r"(a[1]), "r"(a[2]), "r"(a[3]), "r"(b[0]), "r"(b[1]));
}
__device__ __forceinline__ void ldm_x4(uint32_t& r0, uint32_t& r1, uint32_t& r2, uint32_t& r3, uint32_t a) {
    asm volatile("ldmatrix.sync.aligned.m8n8.x4.shared.b16 {%0,%1,%2,%3}, [%4];"
        : "=r"(r0), "=r"(r1), "=r"(r2), "=r"(r3) : "r"(a));
}
__device__ __forceinline__ void ldm_x4t(uint32_t& r0, uint32_t& r1, uint32_t& r2, uint32_t& r3, uint32_t a) {
    asm volatile("ldmatrix.sync.aligned.m8n8.x4.trans.shared.b16 {%0,%1,%2,%3}, [%4];"
        : "=r"(r0), "=r"(r1), "=r"(r2), "=r"(r3) : "r"(a));
}
__device__ __forceinline__ uint32_t packh2(float x, float y) {
    __half2 h = __floats2half2_rn(x, y);
    return *(uint32_t*)&h;
}
__device__ __forceinline__ uint32_t ex2h2(uint32_t x) {
    uint32_t r; asm("ex2.approx.f16x2 %0, %1;" : "=r"(r) : "r"(x));
    return r;
}
// fast SiLU via MUFU ex2 + rcp
__device__ __forceinline__ float silu_f(float z) {
    float e, r;
    float t = -1.4426950408889634f * z;
    asm("ex2.approx.f32 %0, %1;" : "=f"(e) : "f"(t));
    float d = 1.0f + e;
    asm("rcp.approx.f32 %0, %1;" : "=f"(r) : "f"(d));
    return z * r;
}

// ---------------- LayerNorm: warp-per-row, no smem, fp16 out ----------------
__global__ void ln_kernel(const float* __restrict__ x, const float* __restrict__ w,
                          const float* __restrict__ b, __half* __restrict__ out) {
    int lane = threadIdx.x & 31, wrp = threadIdx.x >> 5;
    int row = blockIdx.x * 8 + wrp;
    const float* xr = x + (size_t)row * D;

    float4 v[6];
    float s = 0.0f, sq = 0.0f;
    #pragma unroll
    for (int j = 0; j < 6; j++) {
        v[j] = *(const float4*)(xr + lane * 4 + j * 128);
        s  += (v[j].x + v[j].y) + (v[j].z + v[j].w);
        sq += v[j].x*v[j].x + v[j].y*v[j].y + v[j].z*v[j].z + v[j].w*v[j].w;
    }
    #pragma unroll
    for (int o = 16; o; o >>= 1) {
        s  += __shfl_xor_sync(0xffffffffu, s,  o);
        sq += __shfl_xor_sync(0xffffffffu, sq, o);
    }
    float mu  = s * (1.0f / D);
    float inv = rsqrtf(sq * (1.0f / D) - mu * mu + 1e-5f);

    __half* orow = out + (size_t)row * D;
    #pragma unroll
    for (int j = 0; j < 6; j++) {
        int c = lane * 4 + j * 128;
        float4 wv = *(const float4*)(w + c);
        float4 bv = *(const float4*)(b + c);
        __half2 h0 = __floats2half2_rn((v[j].x - mu) * inv * wv.x + bv.x,
                                       (v[j].y - mu) * inv * wv.y + bv.y);
        __half2 h1 = __floats2half2_rn((v[j].z - mu) * inv * wv.z + bv.z,
                                       (v[j].w - mu) * inv * wv.w + bv.w);
        uint2 pk = make_uint2(*(uint32_t*)&h0, *(uint32_t*)&h1);
        *(uint2*)(orow + c) = pk;
    }
}

// ------------- repack [H,D,HS] QKV weights -> [N rows, K] k-major fp16 (coalesced) -------------
__global__ void repack_kernel(const float* __restrict__ Wq, const float* __restrict__ Wk,
                              const float* __restrict__ Wv, __half* __restrict__ dst) {
    __shared__ float tile[32][33];
    int m = blockIdx.z / HH, h = blockIdx.z % HH;
    const float* W = (m == 0) ? Wq : ((m == 1) ? Wk : Wv);
    const float* Wh = W + (size_t)h * D * HS;
    int e0 = blockIdx.x * 32, d0 = blockIdx.y * 32;
    #pragma unroll
    for (int i = 0; i < 32; i += 8)
        tile[threadIdx.y + i][threadIdx.x] = Wh[(size_t)(d0 + threadIdx.y + i) * HS + e0 + threadIdx.x];
    __syncthreads();
    __half* dm = dst + (size_t)m * DD;
    #pragma unroll
    for (int i = 0; i < 32; i += 8)
        dm[(size_t)(h * HS + e0 + threadIdx.y + i) * D + d0 + threadIdx.x] =
            __float2half_rn(tile[threadIdx.x][threadIdx.y + i]);
}

// ------------- tiled transpose + fp16 convert -------------
__global__ void transpose_kernel(const float* __restrict__ src, __half* __restrict__ dst,
                                 int R, int C) {
    __shared__ float tile[32][33];
    int bx = blockIdx.x * 32, by = blockIdx.y * 32;
    int x = bx + threadIdx.x;
    #pragma unroll
    for (int i = 0; i < 32; i += 8)
        tile[threadIdx.y + i][threadIdx.x] = src[(size_t)(by + threadIdx.y + i) * C + x];
    __syncthreads();
    int x2 = by + threadIdx.x;
    #pragma unroll
    for (int i = 0; i < 32; i += 8)
        dst[(size_t)(bx + threadIdx.y + i) * R + x2] = __float2half_rn(tile[threadIdx.x][threadIdx.y + i]);
}

__global__ void round_kernel(const float* __restrict__ src, __half* __restrict__ dst, int n) {
    int i = blockIdx.x * blockDim.x + threadIdx.x;
    if (i < n) dst[i] = __float2half_rn(src[i]);
}
__global__ void concat3_kernel(const float* __restrict__ a, const float* __restrict__ b,
                               const float* __restrict__ c, float* __restrict__ dst) {
    int i = blockIdx.x * blockDim.x + threadIdx.x;
    if (i < D) dst[i] = a[i];
    else if (i < 2 * D) dst[i] = b[i - D];
    else if (i < 3 * D) dst[i] = c[i - 2 * D];
}
__global__ void concat2_kernel(const float* __restrict__ a, const float* __restrict__ b,
                               float* __restrict__ dst) {
    int i = blockIdx.x * blockDim.x + threadIdx.x;
    if (i < D) dst[i] = a[i];
    else if (i < 2 * D) dst[i] = b[i - D];
}

// =======================================================================================
// fp16 mma.sync GEMM: BM=BN=128, BK=32, 256 threads, 4-stage cp.async, ldmatrix frags.
// =======================================================================================
#define WS     20
#define STAGES 4
#define TILEWW (128 * WS)

template<int ACT, bool RES, bool OUTH>
__global__ __launch_bounds__(256)
void gemm_mma(const __half* __restrict__ A, const __half* __restrict__ Bt,
              const float* __restrict__ bias, const float* __restrict__ res,
              void* __restrict__ Cv, int M, int N, int K) {
    extern __shared__ uint32_t smw[];

    const int tid  = threadIdx.x;
    const int lane = tid & 31, wid = tid >> 5;
    const int warp_m = wid & 1, warp_n = wid >> 1;
    const int bm = blockIdx.y * 128, bn = blockIdx.x * 128;
    const uint32_t sbase = smem_u32(smw);

    const int r0l = tid >> 2, subl = tid & 3;
    const __half* Ag = A + (size_t)(bm + r0l) * K + subl * 8;
    const __half* Bg = Bt + (size_t)(bn + r0l) * K + subl * 8;
    const uint32_t adst0 = sbase + (uint32_t)(r0l * WS + subl * 4) * 4u;
    const uint32_t bdst0 = sbase + (uint32_t)(STAGES * TILEWW + r0l * WS + subl * 4) * 4u;

    const int nt = K >> 5;

    auto prefetch = [&](int kt) {
        int s = kt % STAGES;
        uint32_t ad = adst0 + (uint32_t)(s * TILEWW) * 4u;
        uint32_t bd = bdst0 + (uint32_t)(s * TILEWW) * 4u;
        const __half* ag = Ag + kt * 32;
        const __half* bg = Bg + kt * 32;
        cp_async16(ad, ag);
        cp_async16(ad + (uint32_t)(64 * WS) * 4u, ag + (size_t)64 * K);
        cp_async16(bd, bg);
        cp_async16(bd + (uint32_t)(64 * WS) * 4u, bg + (size_t)64 * K);
    };

    float acc[4][4][4];
    #pragma unroll
    for (int mi = 0; mi < 4; mi++)
        #pragma unroll
        for (int ni = 0; ni < 4; ni++)
            #pragma unroll
            for (int e = 0; e < 4; e++) acc[mi][ni][e] = 0.0f;

    #pragma unroll
    for (int s = 0; s < STAGES - 1; s++) { prefetch(s); cp_commit(); }

    const uint32_t a_l = (uint32_t)((warp_m * 64 + (lane & 15)) * WS) * 4u + (uint32_t)((lane >> 4) * 16);
    const uint32_t b_l = (uint32_t)(STAGES * TILEWW) * 4u +
                         (uint32_t)((warp_n * 32 + (lane & 7) + ((lane >> 4) << 3)) * WS) * 4u +
                         (uint32_t)(((lane >> 3) & 1) * 16);

    for (int kt = 0; kt < nt; kt++) {
        cp_wait<STAGES - 2>();
        __syncthreads();
        if (kt + STAGES - 1 < nt) prefetch(kt + STAGES - 1);
        cp_commit();

        int s = kt % STAGES;
        const uint32_t soff = (uint32_t)(s * TILEWW) * 4u;
        const uint32_t abase_s = sbase + soff + a_l;
        const uint32_t bbase_s = sbase + soff + b_l;

        #pragma unroll
        for (int ks = 0; ks < 2; ks++) {
            const uint32_t koff = (uint32_t)(ks * 32);
            uint32_t af[4][4], bf[4][2];
            #pragma unroll
            for (int mi = 0; mi < 4; mi++)
                ldm_x4(af[mi][0], af[mi][1], af[mi][2], af[mi][3],
                       abase_s + (uint32_t)(mi * 16 * WS) * 4u + koff);
            ldm_x4(bf[0][0], bf[0][1], bf[1][0], bf[1][1], bbase_s + koff);
            ldm_x4(bf[2][0], bf[2][1], bf[3][0], bf[3][1],
                   bbase_s + (uint32_t)(16 * WS) * 4u + koff);
            #pragma unroll
            for (int mi = 0; mi < 4; mi++)
                #pragma unroll
                for (int ni = 0; ni < 4; ni++)
                    mma_f16(acc[mi][ni], af[mi], bf[ni]);
        }
    }

    const int lr = lane >> 2, lc = lane & 3;
    #pragma unroll
    for (int mi = 0; mi < 4; mi++) {
        int r0 = bm + warp_m * 64 + mi * 16 + lr;
        #pragma unroll
        for (int ni = 0; ni < 4; ni++) {
            int c0 = bn + warp_n * 32 + ni * 8 + 2 * lc;
            float b0 = bias[c0], b1 = bias[c0 + 1];
            float v00 = acc[mi][ni][0] + b0, v01 = acc[mi][ni][1] + b1;
            float v10 = acc[mi][ni][2] + b0, v11 = acc[mi][ni][3] + b1;
            if (ACT == 1) { v00 = silu_f(v00); v01 = silu_f(v01); v10 = silu_f(v10); v11 = silu_f(v11); }
            if (RES) {
                const float2 rA = *(const float2*)(res + (size_t)r0 * N + c0);
                const float2 rB = *(const float2*)(res + (size_t)(r0 + 8) * N + c0);
                v00 += rA.x; v01 += rA.y; v10 += rB.x; v11 += rB.y;
            }
            if (OUTH) {
                __half* Ch = (__half*)Cv;
                uint32_t p0 = packh2(v00, v01), p1 = packh2(v10, v11);
                *(uint32_t*)(Ch + (size_t)r0 * N + c0)       = p0;
                *(uint32_t*)(Ch + (size_t)(r0 + 8) * N + c0) = p1;
            } else {
                float* Cf = (float*)Cv;
                *(float2*)(Cf + (size_t)r0 * N + c0)       = make_float2(v00, v01);
                *(float2*)(Cf + (size_t)(r0 + 8) * N + c0) = make_float2(v10, v11);
            }
        }
    }
}

// =======================================================================================
// fp16 tensor-core flash attention: f16x2 exp2 + ones-MMA row sums.
// =======================================================================================
#define KVSTR_B 144
#define KTILE_B (64 * KVSTR_B)
#define ONESH2  0x3C003C00u

__global__ __launch_bounds__(256)
void attn_tc(const __half* __restrict__ Q, int ldq,
             const __half* __restrict__ Kg, const __half* __restrict__ Vg, int ldkv,
             const float* __restrict__ xres, float* __restrict__ out,
             int Tq, int Tkv) {
    extern __shared__ uint32_t smw[];
    const uint32_t sbase = smem_u32(smw);

    const int tid = threadIdx.x;
    const int lane = tid & 31, wid = tid >> 5;
    const int lr = lane >> 2, lc = lane & 3;
    const int h = blockIdx.y, b = blockIdx.z;
    const int brow = b * Tq + blockIdx.x * 128;
    const int m0 = wid * 16;

    const __half* Kb = Kg + (size_t)b * Tkv * ldkv + h * HS;
    const __half* Vb = Vg + (size_t)b * Tkv * ldkv + h * HS;

    const float SC2 = 0.125f * 1.4426950408889634f;
    uint32_t qf[4][4];
    {
        const __half* Qp = Q + (size_t)(brow + m0) * ldq + h * HS;
        #pragma unroll
        for (int ks = 0; ks < 4; ks++) {
            int c = ks * 16 + 2 * lc;
            #pragma unroll
            for (int e = 0; e < 4; e++) {
                int rr = (e & 1) ? lr + 8 : lr;
                int cc = c + ((e >> 1) ? 8 : 0);
                __half2 hv = *(const __half2*)(Qp + (size_t)rr * ldq + cc);
                float2 f = __half22float2(hv);
                qf[ks][e] = packh2(f.x * SC2, f.y * SC2);
            }
        }
    }

    const int rl = lane & 7;
    const uint32_t loff_k = (uint32_t)(rl * KVSTR_B + ((lane >> 3) * 16));
    const uint32_t loff_v = (uint32_t)(((((lane >> 3) & 1) * 8 + rl) * KVSTR_B) + ((lane >> 4) * 16));

    const int lrow = tid >> 3, lsub = tid & 7;
    auto prefetch = [&](int kt) {
        int buf = kt & 1;
        uint32_t kdst = sbase + buf * KTILE_B + lrow * KVSTR_B + lsub * 16;
        uint32_t vdst = kdst + 2 * KTILE_B;
        const __half* kp = Kb + (size_t)(kt * 64 + lrow) * ldkv + lsub * 8;
        const __half* vp = Vb + (size_t)(kt * 64 + lrow) * ldkv + lsub * 8;
        cp_async16(kdst, kp);
        cp_async16(kdst + 32 * KVSTR_B, kp + (size_t)32 * ldkv);
        cp_async16(vdst, vp);
        cp_async16(vdst + 32 * KVSTR_B, vp + (size_t)32 * ldkv);
    };

    float oacc[8][4];
    #pragma unroll
    for (int i = 0; i < 8; i++)
        #pragma unroll
        for (int e = 0; e < 4; e++) oacc[i][e] = 0.0f;
    float lacc[4] = {0.0f, 0.0f, 0.0f, 0.0f};
    float mstate0 = -1e30f, mstate1 = -1e30f;

    const int nt = Tkv >> 6;
    prefetch(0); cp_commit();

    for (int kt = 0; kt < nt; kt++) {
        if (kt + 1 < nt) { prefetch(kt + 1); cp_commit(); cp_wait<1>(); }
        else             { cp_wait<0>(); }
        __syncthreads();

        const uint32_t kbase = sbase + (kt & 1) * KTILE_B;
        const uint32_t vbase = kbase + 2 * KTILE_B;

        float sacc[8][4];
        #pragma unroll
        for (int nf = 0; nf < 8; nf++)
            #pragma unroll
            for (int e = 0; e < 4; e++) sacc[nf][e] = 0.0f;

        #pragma unroll
        for (int nf = 0; nf < 8; nf++) {
            uint32_t k0, k1, k2, k3, k4, k5, k6, k7;
            uint32_t base = kbase + nf * (8 * KVSTR_B) + loff_k;
            ldm_x4(k0, k1, k2, k3, base);
            ldm_x4(k4, k5, k6, k7, base + 64);
            uint32_t bf[2];
            bf[0] = k0; bf[1] = k1; mma_f16(sacc[nf], qf[0], bf);
            bf[0] = k2; bf[1] = k3; mma_f16(sacc[nf], qf[1], bf);
            bf[0] = k4; bf[1] = k5; mma_f16(sacc[nf], qf[2], bf);
            bf[0] = k6; bf[1] = k7; mma_f16(sacc[nf], qf[3], bf);
        }

        float mx0 = -1e30f, mx1 = -1e30f;
        #pragma unroll
        for (int nf = 0; nf < 8; nf++) {
            mx0 = fmaxf(mx0, fmaxf(sacc[nf][0], sacc[nf][1]));
            mx1 = fmaxf(mx1, fmaxf(sacc[nf][2], sacc[nf][3]));
        }
        mx0 = fmaxf(mx0, __shfl_xor_sync(0xffffffffu, mx0, 1));
        mx0 = fmaxf(mx0, __shfl_xor_sync(0xffffffffu, mx0, 2));
        mx1 = fmaxf(mx1, __shfl_xor_sync(0xffffffffu, mx1, 1));
        mx1 = fmaxf(mx1, __shfl_xor_sync(0xffffffffu, mx1, 2));
        float mn0 = fmaxf(mstate0, mx0), mn1 = fmaxf(mstate1, mx1);
        float corr0 = exp2f(mstate0 - mn0), corr1 = exp2f(mstate1 - mn1);
        mstate0 = mn0; mstate1 = mn1;

        uint32_t pf[8][2];
        #pragma unroll
        for (int nf = 0; nf < 8; nf++) {
            pf[nf][0] = ex2h2(packh2(sacc[nf][0] - mn0, sacc[nf][1] - mn0));
            pf[nf][1] = ex2h2(packh2(sacc[nf][2] - mn1, sacc[nf][3] - mn1));
        }

        #pragma unroll
        for (int nf = 0; nf < 8; nf++) {
            oacc[nf][0] *= corr0; oacc[nf][1] *= corr0;
            oacc[nf][2] *= corr1; oacc[nf][3] *= corr1;
        }
        lacc[0] *= corr0; lacc[1] *= corr0; lacc[2] *= corr1; lacc[3] *= corr1;

        const uint32_t onesf[2] = {ONESH2, ONESH2};
        #pragma unroll
        for (int kg = 0; kg < 4; kg++) {
            uint32_t af[4];
            af[0] = pf[2*kg][0];
            af[1] = pf[2*kg][1];
            af[2] = pf[2*kg+1][0];
            af[3] = pf[2*kg+1][1];
            mma_f16(lacc, af, onesf);
            #pragma unroll
            for (int nfp = 0; nfp < 4; nfp++) {
                uint32_t v0, v1, v2, v3;
                ldm_x4t(v0, v1, v2, v3, vbase + kg * (16 * KVSTR_B) + nfp * 32 + loff_v);
                uint32_t bf[2];
                bf[0] = v0; bf[1] = v1; mma_f16(oacc[2*nfp],     af, bf);
                bf[0] = v2; bf[1] = v3; mma_f16(oacc[2*nfp + 1], af, bf);
            }
        }
        __syncthreads();
    }

    float inv0 = 1.0f / lacc[0], inv1 = 1.0f / lacc[2];
    int row0 = brow + m0 + lr, row1 = row0 + 8;
    #pragma unroll
    for (int nf = 0; nf < 8; nf++) {
        int col = h * HS + nf * 8 + 2 * lc;
        float2 rA = *(const float2*)(xres + (size_t)row0 * D + col);
        float2 rB = *(const float2*)(xres + (size_t)row1 * D + col);
        *(float2*)(out + (size_t)row0 * D + col) =
            make_float2(rA.x + oacc[nf][0] * inv0, rA.y + oacc[nf][1] * inv0);
        *(float2*)(out + (size_t)row1 * D + col) =
            make_float2(rB.x + oacc[nf][2] * inv1, rB.y + oacc[nf][3] * inv1);
    }
}

// ---------------- host launch: two half-pipelines, interleaved enqueue ----------------
extern "C" void kernel_launch(void* const* d_in, const int* in_sizes, int n_in,
                              void* d_out, int out_size) {
    const float* x0    = (const float*)d_in[0];
    const float* ctx   = (const float*)d_in[1];
    const float* ln1_w = (const float*)d_in[2];
    const float* ln1_b = (const float*)d_in[3];
    const float* sWq   = (const float*)d_in[4];
    const float* sbq   = (const float*)d_in[5];
    const float* sWk   = (const float*)d_in[6];
    const float* sbk   = (const float*)d_in[7];
    const float* sWv   = (const float*)d_in[8];
    const float* sbv   = (const float*)d_in[9];
    const float* ln2_w = (const float*)d_in[10];
    const float* ln2_b = (const float*)d_in[11];
    const float* cWq   = (const float*)d_in[12];
    const float* cbq   = (const float*)d_in[13];
    const float* cWk   = (const float*)d_in[14];
    const float* cbk   = (const float*)d_in[15];
    const float* cWv   = (const float*)d_in[16];
    const float* cbv   = (const float*)d_in[17];
    const float* ln3_w = (const float*)d_in[18];
    const float* ln3_b = (const float*)d_in[19];
    const float* W1    = (const float*)d_in[20];
    const float* b1    = (const float*)d_in[21];
    const float* W2    = (const float*)d_in[22];
    const float* b2    = (const float*)d_in[23];
    float* outp = (float*)d_out;

    __half *ln, *q, *qkv, *kvc, *ctr, *ffh, *wts, *wtc, *w1t, *w2t;
    float *x1, *x2, *bqkv, *bkvc;
    cudaGetSymbolAddress((void**)&ln,   g_ln);
    cudaGetSymbolAddress((void**)&q,    g_q);
    cudaGetSymbolAddress((void**)&qkv,  g_qkv);
    cudaGetSymbolAddress((void**)&kvc,  g_kvc);
    cudaGetSymbolAddress((void**)&x1,   g_x1);
    cudaGetSymbolAddress((void**)&x2,   g_x2);
    cudaGetSymbolAddress((void**)&ctr,  g_ctx);
    cudaGetSymbolAddress((void**)&ffh,  g_ffh);
    cudaGetSymbolAddress((void**)&wts,  g_wts);
    cudaGetSymbolAddress((void**)&wtc,  g_wtc);
    cudaGetSymbolAddress((void**)&w1t,  g_w1t);
    cudaGetSymbolAddress((void**)&w2t,  g_w2t);
    cudaGetSymbolAddress((void**)&bqkv, g_bqkv);
    cudaGetSymbolAddress((void**)&bkvc, g_bkvc);

    const int SMEM_GEMM = STAGES * TILEWW * 2 * 4;   // 81920 B
    const int SMEM_ATTN = 4 * KTILE_B;               // 36864 B

    static cudaStream_t s1 = nullptr, s2 = nullptr;
    static cudaEvent_t eFork, eW1, eW2, eKV, eW3, eDone;
    static bool inited = false;
    if (!inited) {
        cudaStreamCreateWithFlags(&s1, cudaStreamNonBlocking);
        cudaStreamCreateWithFlags(&s2, cudaStreamNonBlocking);
        cudaEventCreateWithFlags(&eFork, cudaEventDisableTiming);
        cudaEventCreateWithFlags(&eW1,   cudaEventDisableTiming);
        cudaEventCreateWithFlags(&eW2,   cudaEventDisableTiming);
        cudaEventCreateWithFlags(&eKV,   cudaEventDisableTiming);
        cudaEventCreateWithFlags(&eW3,   cudaEventDisableTiming);
        cudaEventCreateWithFlags(&eDone, cudaEventDisableTiming);
        cudaFuncSetAttribute(gemm_mma<0, false, true >, cudaFuncAttributeMaxDynamicSharedMemorySize, SMEM_GEMM);
        cudaFuncSetAttribute(gemm_mma<1, false, true >, cudaFuncAttributeMaxDynamicSharedMemorySize, SMEM_GEMM);
        cudaFuncSetAttribute(gemm_mma<0, true,  false>, cudaFuncAttributeMaxDynamicSharedMemorySize, SMEM_GEMM);
        cudaFuncSetAttribute(attn_tc, cudaFuncAttributeMaxDynamicSharedMemorySize, SMEM_ATTN);
        inited = true;
    }

    dim3 gqkvH(3 * D / 128, MH / 128);   // (18, 32)
    dim3 gqH  (D / 128, MH / 128);       // (6, 32)
    dim3 gkvc (2 * D / 128, MKV / 128);  // (12, 16)
    dim3 gff1H(FFD / 128, MH / 128);     // (24, 32)
    dim3 gff2H(D / 128, MH / 128);       // (6, 32)
    dim3 gatnH(TT / 128, HH, BB / 2);    // (8, 12, 4)

    // ---- fork: weight prep on s1 ----
    cudaEventRecord(eFork, 0);
    cudaStreamWaitEvent(s1, eFork, 0);
    cudaStreamWaitEvent(s2, eFork, 0);

    repack_kernel<<<dim3(HS / 32, D / 32, 3 * HH), dim3(32, 8), 0, s1>>>(sWq, sWk, sWv, wts);
    concat3_kernel<<<9, 256, 0, s1>>>(sbq, sbk, sbv, bqkv);
    cudaEventRecord(eW1, s1);
    round_kernel<<<(MKV * D + 255) / 256, 256, 0, s1>>>(ctx, ctr, MKV * D);
    repack_kernel<<<dim3(HS / 32, D / 32, 3 * HH), dim3(32, 8), 0, s1>>>(cWq, cWk, cWv, wtc);
    concat2_kernel<<<6, 256, 0, s1>>>(cbk, cbv, bkvc);
    cudaEventRecord(eW2, s1);
    gemm_mma<0, false, true><<<gkvc, 256, SMEM_GEMM, s1>>>(ctr, wtc + DD, bkvc, nullptr, kvc, MKV, 2 * D, D);
    cudaEventRecord(eKV, s1);
    transpose_kernel<<<dim3(FFD / 32, D / 32), dim3(32, 8), 0, s1>>>(W1, w1t, D, FFD);
    transpose_kernel<<<dim3(D / 32, FFD / 32), dim3(32, 8), 0, s1>>>(W2, w2t, FFD, D);
    cudaEventRecord(eW3, s1);

    // ---- two half-pipelines, interleaved enqueue (A = main stream, B = s2) ----
    const size_t oD  = (size_t)MH * D;
    const size_t o3D = (size_t)MH * 3 * D;
    const size_t oFF = (size_t)MH * FFD;
    const size_t oKV = (size_t)(BB / 2) * TCC * 2 * D;

    // block 1
    ln_kernel<<<MH / 8, 256, 0, 0 >>>(x0,      ln1_w, ln1_b, ln);
    ln_kernel<<<MH / 8, 256, 0, s2>>>(x0 + oD, ln1_w, ln1_b, ln + oD);
    cudaStreamWaitEvent(0,  eW1, 0);
    cudaStreamWaitEvent(s2, eW1, 0);
    gemm_mma<0, false, true><<<gqkvH, 256, SMEM_GEMM, 0 >>>(ln,      wts, bqkv, nullptr, qkv,       MQ, 3 * D, D);
    gemm_mma<0, false, true><<<gqkvH, 256, SMEM_GEMM, s2>>>(ln + oD, wts, bqkv, nullptr, qkv + o3D, MQ, 3 * D, D);
    attn_tc<<<gatnH, 256, SMEM_ATTN, 0 >>>(qkv,       3 * D, qkv + D,       qkv + 2 * D,       3 * D, x0,      x1,      TT, TT);
    attn_tc<<<gatnH, 256, SMEM_ATTN, s2>>>(qkv + o3D, 3 * D, qkv + o3D + D, qkv + o3D + 2 * D, 3 * D, x0 + oD, x1 + oD, TT, TT);

    // block 2
    ln_kernel<<<MH / 8, 256, 0, 0 >>>(x1,      ln2_w, ln2_b, ln);
    ln_kernel<<<MH / 8, 256, 0, s2>>>(x1 + oD, ln2_w, ln2_b, ln + oD);
    cudaStreamWaitEvent(0,  eW2, 0);
    cudaStreamWaitEvent(s2, eW2, 0);
    gemm_mma<0, false, true><<<gqH, 256, SMEM_GEMM, 0 >>>(ln,      wtc, cbq, nullptr, q,      MQ, D, D);
    gemm_mma<0, false, true><<<gqH, 256, SMEM_GEMM, s2>>>(ln + oD, wtc, cbq, nullptr, q + oD, MQ, D, D);
    cudaStreamWaitEvent(0,  eKV, 0);
    cudaStreamWaitEvent(s2, eKV, 0);
    attn_tc<<<gatnH, 256, SMEM_ATTN, 0 >>>(q,      D, kvc,       kvc + D,       2 * D, x1,      x2,      TT, TCC);
    attn_tc<<<gatnH, 256, SMEM_ATTN, s2>>>(q + oD, D, kvc + oKV, kvc + oKV + D, 2 * D, x1 + oD, x2 + oD, TT, TCC);

    // block 3
    ln_kernel<<<MH / 8, 256, 0, 0 >>>(x2,      ln3_w, ln3_b, ln);
    ln_kernel<<<MH / 8, 256, 0, s2>>>(x2 + oD, ln3_w, ln3_b, ln + oD);
    cudaStreamWaitEvent(0,  eW3, 0);
    cudaStreamWaitEvent(s2, eW3, 0);
    gemm_mma<1, false, true ><<<gff1H, 256, SMEM_GEMM, 0 >>>(ln,       w1t, b1, nullptr, ffh,       MQ, FFD, D);
    gemm_mma<1, false, true ><<<gff1H, 256, SMEM_GEMM, s2>>>(ln + oD,  w1t, b1, nullptr, ffh + oFF, MQ, FFD, D);
    gemm_mma<0, true,  false><<<gff2H, 256, SMEM_GEMM, 0 >>>(ffh,       w2t, b2, x2,      outp,      MQ, D, FFD);
    gemm_mma<0, true,  false><<<gff2H, 256, SMEM_GEMM, s2>>>(ffh + oFF, w2t, b2, x2 + oD, outp + oD, MQ, D, FFD);

    cudaEventRecord(eDone, s2);
    cudaStreamWaitEvent(0, eDone, 0);
}